// round 7
// baseline (speedup 1.0000x reference)
#include <cuda_runtime.h>
#include <math.h>

#define NB   128   // N dialogues
#define LSEQ 64    // L
#define EDIM 300
#define HDIM 300
#define KF   40    // KEFF
#define NQ   127   // N-1
#define NHOPS 3
#define NCLS 6

#define SCAN_BLOCKS 120   // 2 dirs x 60 slices of 5 units
#define SCAN_THREADS 160  // 32 batch-rows x 5 units
#define KC 20             // k-chunk staged in smem (300 = 15*20)

// ---------------- scratch (device globals; no allocation) ----------------
__device__ float g_gi_utt[(size_t)LSEQ * NB * 1800];     // [t*128+b, 1800]
__device__ float g_h_utt[2][2 * NB * HDIM];
__device__ float g_maxpool[NB * 2 * HDIM];
__device__ float g_u[NB * HDIM];
__device__ float g_inp0[KF * NQ * HDIM];                 // ctx_t time-major
__device__ float g_gi_ctx[(size_t)KF * NQ * 1800];
__device__ float g_seq_ctx[2 * KF * NQ * HDIM];          // [dir, t, i, j]
__device__ float g_h_ctx[2][2 * NQ * HDIM];
__device__ float g_mem[KF * NQ * HDIM];                  // time-major [k,i,j]
__device__ float g_xr[(size_t)KF * NQ * 1800];
__device__ float g_xw[(size_t)KF * NQ * 1800];
__device__ float g_gates[KF * NQ];
__device__ float g_query[NQ * HDIM];
__device__ float g_h_att[2][2 * NQ * HDIM];

// software grid barrier state
__device__ unsigned g_bar_cnt = 0;
__device__ volatile unsigned g_bar_gen = 0;

__device__ __forceinline__ float sigf(float x) { return 1.f / (1.f + expf(-x)); }

__device__ __forceinline__ void gsync(int nb, unsigned& gen) {
    __syncthreads();
    if (threadIdx.x == 0) {
        unsigned target = gen + 1;
        __threadfence();
        unsigned prev = atomicAdd(&g_bar_cnt, 1u);
        if (prev == (unsigned)nb - 1) {
            atomicExch(&g_bar_cnt, 0u);
            __threadfence();
            g_bar_gen = target;
        } else {
            while (g_bar_gen != target) __nanosleep(20);
            __threadfence();
        }
    }
    __syncthreads();
    gen++;
}

// ---------------- generic GEMM: C = A(MxK) @ W(NxK)^T + bias, opt gather/tanh ----
#define GTM 64
#define GTN 64
#define GTK 16

template<int GATHER, int EPI>
__global__ __launch_bounds__(256)
void gemm_kernel(const float* __restrict__ A, int lda,
                 const float* __restrict__ W,
                 const float* __restrict__ bias,
                 float* __restrict__ C, int ldc,
                 int M, int N, int K,
                 const float* __restrict__ emb,
                 const int* __restrict__ ids)
{
    __shared__ float As[GTK][GTM + 1];
    __shared__ float Bs[GTK][GTN + 1];
    __shared__ int   rowid[GTM];
    const int tid = threadIdx.x;
    const int m0 = blockIdx.y * GTM;
    const int n0 = blockIdx.x * GTN;

    if (GATHER) {
        if (tid < GTM) {
            int m = m0 + tid;
            int t = m >> 7, b = m & 127;          // m = t*128 + b
            rowid[tid] = (m < M) ? ids[b * LSEQ + t] : 0;
        }
        __syncthreads();
    }

    float acc[4][4] = {};
    const int mt = tid >> 4;   // 0..15
    const int nt = tid & 15;   // 0..15

    for (int k0 = 0; k0 < K; k0 += GTK) {
#pragma unroll
        for (int i = 0; i < 4; i++) {
            int idx = tid + i * 256;
            int mm = idx >> 4, kk = idx & 15;
            int m = m0 + mm, k = k0 + kk;
            float v = 0.f;
            if (m < M && k < K) {
                if (GATHER) v = emb[(long)rowid[mm] * K + k];
                else        v = A[(long)m * lda + k];
            }
            As[kk][mm] = v;
        }
#pragma unroll
        for (int i = 0; i < 4; i++) {
            int idx = tid + i * 256;
            int nn = idx >> 4, kk = idx & 15;
            int n = n0 + nn, k = k0 + kk;
            Bs[kk][nn] = (n < N && k < K) ? W[(long)n * K + k] : 0.f;
        }
        __syncthreads();
#pragma unroll
        for (int kk = 0; kk < GTK; kk++) {
            float a[4], b[4];
#pragma unroll
            for (int i = 0; i < 4; i++) a[i] = As[kk][mt * 4 + i];
#pragma unroll
            for (int j = 0; j < 4; j++) b[j] = Bs[kk][nt * 4 + j];
#pragma unroll
            for (int i = 0; i < 4; i++)
#pragma unroll
                for (int j = 0; j < 4; j++)
                    acc[i][j] += a[i] * b[j];
        }
        __syncthreads();
    }
#pragma unroll
    for (int i = 0; i < 4; i++) {
        int m = m0 + mt * 4 + i;
        if (m >= M) continue;
#pragma unroll
        for (int j = 0; j < 4; j++) {
            int n = n0 + nt * 4 + j;
            if (n >= N) continue;
            float v = acc[i][j] + bias[n];
            if (EPI == 1) v = tanhf(v);
            C[(long)m * ldc + n] = v;
        }
    }
}

// ---------------- persistent GRU scan (all T steps in one launch) ----------
// MODE 0: utt (mask + reversed gi index + register max-pool)
// MODE 1: ctx (full lengths, store per-step output sequence)
// Block: dir = bid/60, units j0..j0+4 (all 3 gates). Weights persist in smem.
template<int MODE>
__global__ __launch_bounds__(SCAN_THREADS, 1)
void gru_scan_kernel(float* __restrict__ h0, float* __restrict__ h1,
                     const float* __restrict__ gi,      // [T*B, 1800]
                     const float* __restrict__ Whh,     // [2,900,300]
                     const float* __restrict__ bhh,     // [2,900]
                     const int*   __restrict__ seq_lens,
                     float* __restrict__ maxpool,       // [B, 600]
                     float* __restrict__ seqout,        // [2,T,B,300]
                     int B, int T)
{
    __shared__ float Wf[15 * HDIM];     // [col(g*5+jj)][k], k contiguous
    __shared__ float Hs[128 * KC];      // [b][kk], kk contiguous

    const int tid = threadIdx.x;
    const int bid = blockIdx.x;
    const int dir = bid / 60;
    const int j0  = (bid % 60) * 5;
    const int jj   = tid % 5;
    const int brow = tid / 5;           // 0..31
    const int dirbase = dir * B * HDIM;

    unsigned gen = g_bar_gen;

    // load persistent weight slice: 15 rows (3 gates x 5 units) x 300
    for (int idx = tid; idx < 15 * HDIM; idx += SCAN_THREADS) {
        int col = idx / HDIM, k = idx % HDIM;
        int g = col / 5, ju = col % 5;
        Wf[col * HDIM + k] = Whh[((long)dir * 900 + g * 300 + (j0 + ju)) * HDIM + k];
    }

    const float* wr_p = Wf + (0 + jj) * HDIM;
    const float* wz_p = Wf + (5 + jj) * HDIM;
    const float* wn_p = Wf + (10 + jj) * HDIM;

    const int j = j0 + jj;
    const float bhr = bhh[dir * 900 + j];
    const float bhz = bhh[dir * 900 + 300 + j];
    const float bhn = bhh[dir * 900 + 600 + j];

    float mpv[4];
#pragma unroll
    for (int i = 0; i < 4; i++) mpv[i] = -1e30f;

    int cur = 0;
    for (int t = 0; t < T; t++) {
        const float* hp = cur ? h1 : h0;
        float*       hn = cur ? h0 : h1;

        float accr[4] = {}, accz[4] = {}, accn[4] = {};
        for (int c = 0; c < HDIM / KC; c++) {
            const int k0 = c * KC;
            __syncthreads();
            // stage h chunk: 128 x KC floats (float4 loads)
            for (int idx = tid; idx < 128 * (KC / 4); idx += SCAN_THREADS) {
                int b = idx / (KC / 4), q = idx % (KC / 4);
                float4 v = make_float4(0.f, 0.f, 0.f, 0.f);
                if (b < B) v = *(const float4*)&hp[dirbase + b * HDIM + k0 + q * 4];
                *(float4*)&Hs[b * KC + q * 4] = v;
            }
            __syncthreads();
#pragma unroll
            for (int kk = 0; kk < KC / 2; kk++) {
                float2 wr = *(const float2*)(wr_p + k0 + 2 * kk);
                float2 wz = *(const float2*)(wz_p + k0 + 2 * kk);
                float2 wn = *(const float2*)(wn_p + k0 + 2 * kk);
#pragma unroll
                for (int i = 0; i < 4; i++) {
                    float2 h2 = *(const float2*)&Hs[(brow + 32 * i) * KC + 2 * kk];
                    accr[i] = fmaf(h2.x, wr.x, fmaf(h2.y, wr.y, accr[i]));
                    accz[i] = fmaf(h2.x, wz.x, fmaf(h2.y, wz.y, accz[i]));
                    accn[i] = fmaf(h2.x, wn.x, fmaf(h2.y, wn.y, accn[i]));
                }
            }
        }

        // epilogue: each thread owns (4 batches, unit j, all gates)
#pragma unroll
        for (int i = 0; i < 4; i++) {
            int b = brow + 32 * i;
            if (b >= B) continue;
            float hold = hp[dirbase + b * HDIM + j];
            int trow; bool mask = true;
            if (MODE == 0) {
                int len = seq_lens[b];
                mask = (t < len);
                trow = (dir == 0) ? t : max(len - 1 - t, 0);
            } else {
                trow = (dir == 0) ? t : (T - 1 - t);
            }
            const float* gr = gi + ((size_t)trow * B + b) * 1800 + dir * 900 + j;
            float r = sigf(gr[0]   + accr[i] + bhr);
            float z = sigf(gr[300] + accz[i] + bhz);
            float n = tanhf(gr[600] + r * (accn[i] + bhn));
            float hnew = (1.f - z) * n + z * hold;
            if (MODE == 0) {
                hn[dirbase + b * HDIM + j] = mask ? hnew : hold;
                mpv[i] = fmaxf(mpv[i], mask ? hnew : 0.f);
            } else {
                hn[dirbase + b * HDIM + j] = hnew;
                seqout[(((size_t)dir * T + t) * B + b) * HDIM + j] = hnew;
            }
        }
        cur ^= 1;
        gsync(SCAN_BLOCKS, gen);
    }

    if (MODE == 0) {
#pragma unroll
        for (int i = 0; i < 4; i++) {
            int b = brow + 32 * i;
            if (b < B) maxpool[b * (2 * HDIM) + dir * HDIM + j] = mpv[i];
        }
    }
}

// ---------------- persistent attention-GRU scan (one hop, 40 steps) --------
__global__ __launch_bounds__(SCAN_THREADS, 1)
void att_scan_kernel(float* __restrict__ h0, float* __restrict__ h1,
                     const float* __restrict__ xr,   // [40*127, 1800]
                     const float* __restrict__ xw,
                     const float* __restrict__ Ur,   // [3,2,300,300]
                     const float* __restrict__ Uw,
                     const float* __restrict__ bur,  // [3,2,300]
                     const float* __restrict__ bu,
                     const float* __restrict__ gates, // [40*127]
                     int hop)
{
    __shared__ float Wf[10 * HDIM];     // cols 0..4 = Ur[jj], 5..9 = Uw[jj]
    __shared__ float Hs[128 * KC];

    const int tid = threadIdx.x;
    const int bid = blockIdx.x;
    const int dir = bid / 60;
    const int j0  = (bid % 60) * 5;
    const int jj   = tid % 5;
    const int brow = tid / 5;
    const int wd   = hop * 2 + dir;
    const int dirbase = dir * NQ * HDIM;

    unsigned gen = g_bar_gen;

    for (int idx = tid; idx < 10 * HDIM; idx += SCAN_THREADS) {
        int col = idx / HDIM, k = idx % HDIM;
        int g = col / 5, ju = col % 5;
        const float* Wsrc = (g == 0) ? Ur : Uw;
        Wf[col * HDIM + k] = Wsrc[((long)wd * 300 + (j0 + ju)) * HDIM + k];
    }

    const float* wr_p = Wf + jj * HDIM;
    const float* ww_p = Wf + (5 + jj) * HDIM;

    const int j = j0 + jj;
    const float burv = bur[wd * 300 + j];
    const float buv  = bu[wd * 300 + j];

    int cur = 0;
    for (int t = 0; t < KF; t++) {
        const float* hp = cur ? h1 : h0;
        float*       hn = cur ? h0 : h1;

        float accr[4] = {}, accw[4] = {};
        for (int c = 0; c < HDIM / KC; c++) {
            const int k0 = c * KC;
            __syncthreads();
            for (int idx = tid; idx < 128 * (KC / 4); idx += SCAN_THREADS) {
                int b = idx / (KC / 4), q = idx % (KC / 4);
                float4 v = make_float4(0.f, 0.f, 0.f, 0.f);
                if (b < NQ) v = *(const float4*)&hp[dirbase + b * HDIM + k0 + q * 4];
                *(float4*)&Hs[b * KC + q * 4] = v;
            }
            __syncthreads();
#pragma unroll
            for (int kk = 0; kk < KC / 2; kk++) {
                float2 wr = *(const float2*)(wr_p + k0 + 2 * kk);
                float2 ww = *(const float2*)(ww_p + k0 + 2 * kk);
#pragma unroll
                for (int i = 0; i < 4; i++) {
                    float2 h2 = *(const float2*)&Hs[(brow + 32 * i) * KC + 2 * kk];
                    accr[i] = fmaf(h2.x, wr.x, fmaf(h2.y, wr.y, accr[i]));
                    accw[i] = fmaf(h2.x, ww.x, fmaf(h2.y, ww.y, accw[i]));
                }
            }
        }

        const int tt = (dir == 0) ? t : (KF - 1 - t);
#pragma unroll
        for (int i = 0; i < 4; i++) {
            int b = brow + 32 * i;
            if (b >= NQ) continue;
            float hold = hp[dirbase + b * HDIM + j];
            size_t xrow = ((size_t)tt * NQ + b) * 1800 + wd * 300 + j;
            float r  = sigf(xr[xrow] + accr[i] + burv);
            float ht = tanhf(xw[xrow] + r * (accw[i] + buv));
            float g  = gates[tt * NQ + b];
            hn[dirbase + b * HDIM + j] = g * ht + (1.f - g) * hold;
        }
        cur ^= 1;
        gsync(SCAN_BLOCKS, gen);
    }
}

// ---------------- small kernels ----------------
__global__ void fillk(float* p, float v, int n) {
    int i = blockIdx.x * blockDim.x + threadIdx.x;
    if (i < n) p[i] = v;
}

__global__ void build_inp0(const float* __restrict__ u, float* __restrict__ inp0) {
    int idx = blockIdx.x * blockDim.x + threadIdx.x;
    if (idx >= KF * NQ * HDIM) return;
    int j = idx % HDIM;
    int r = idx / HDIM;
    int i = r % NQ;
    int k = r / NQ;
    int src = (i + 1) - KF + k;
    inp0[idx] = (src >= 0) ? u[src * HDIM + j] : 0.f;
}

__global__ void membank_kernel(const float* __restrict__ inp0,
                               const float* __restrict__ seq,
                               float* __restrict__ mem) {
    int idx = blockIdx.x * blockDim.x + threadIdx.x;
    if (idx >= KF * NQ * HDIM) return;
    int j = idx % HDIM;
    int r = idx / HDIM;
    int i = r % NQ;
    int k = r / NQ;
    float f = seq[((long)k) * NQ * HDIM + i * HDIM + j];
    float b = seq[((long)KF + (KF - 1 - k)) * NQ * HDIM + i * HDIM + j];
    mem[idx] = inp0[idx] + f + b;
}

__global__ void score_kernel(const float* __restrict__ query,
                             const float* __restrict__ mem,
                             float* __restrict__ gates) {
    int b = blockIdx.x;                 // 0..126
    int tid = threadIdx.x;              // 128
    int lane = tid & 31, w = tid >> 5;
    __shared__ float q[HDIM];
    __shared__ float logit[KF];
    for (int i = tid; i < HDIM; i += 128) q[i] = query[b * HDIM + i];
    __syncthreads();
    for (int k = w; k < KF; k += 4) {
        const float* mrow = mem + ((long)k * NQ + b) * HDIM;
        float s = 0.f;
        for (int i = lane; i < HDIM; i += 32) s += q[i] * mrow[i];
        for (int o = 16; o > 0; o >>= 1) s += __shfl_xor_sync(0xffffffffu, s, o);
        if (lane == 0) logit[k] = (k >= KF - 1 - b) ? s : -1e10f;
    }
    __syncthreads();
    if (w == 0) {
        float m = -INFINITY;
        for (int k = lane; k < KF; k += 32) m = fmaxf(m, logit[k]);
        for (int o = 16; o > 0; o >>= 1) m = fmaxf(m, __shfl_xor_sync(0xffffffffu, m, o));
        float ssum = 0.f;
        for (int k = lane; k < KF; k += 32) { float e = expf(logit[k] - m); logit[k] = e; ssum += e; }
        for (int o = 16; o > 0; o >>= 1) ssum += __shfl_xor_sync(0xffffffffu, ssum, o);
        for (int k = lane; k < KF; k += 32) gates[k * NQ + b] = logit[k] / ssum;
    }
}

__global__ void add2_kernel(float* __restrict__ q,
                            const float* __restrict__ hf,
                            const float* __restrict__ hb, int n) {
    int i = blockIdx.x * blockDim.x + threadIdx.x;
    if (i < n) q[i] += hf[i] + hb[i];
}

__global__ void cls_kernel(const float* __restrict__ u,
                           const float* __restrict__ query,
                           const float* __restrict__ cls_w,
                           const float* __restrict__ cls_b,
                           float* __restrict__ out) {
    int row = blockIdx.x;               // 0..127
    int w = threadIdx.x >> 5, lane = threadIdx.x & 31;   // 192 threads = 6 warps
    const float* s = (row == 0) ? u : (query + (row - 1) * HDIM);
    float acc = 0.f;
    for (int i = lane; i < HDIM; i += 32) acc += s[i] * cls_w[w * HDIM + i];
    for (int o = 16; o > 0; o >>= 1) acc += __shfl_xor_sync(0xffffffffu, acc, o);
    if (lane == 0) out[row * NCLS + w] = acc + cls_b[w];
}

// ---------------- host orchestration ----------------
extern "C" void kernel_launch(void* const* d_in, const int* in_sizes, int n_in,
                              void* d_out, int out_size) {
    const int*   ids      = (const int*)d_in[0];
    const int*   seq_lens = (const int*)d_in[1];
    const float* emb      = (const float*)d_in[2];
    const float* utt_Wih  = (const float*)d_in[3];
    const float* utt_Whh  = (const float*)d_in[4];
    const float* utt_bih  = (const float*)d_in[5];
    const float* utt_bhh  = (const float*)d_in[6];
    const float* lin_w    = (const float*)d_in[7];
    const float* lin_b    = (const float*)d_in[8];
    const float* ctx_Wih  = (const float*)d_in[9];
    const float* ctx_Whh  = (const float*)d_in[10];
    const float* ctx_bih  = (const float*)d_in[11];
    const float* ctx_bhh  = (const float*)d_in[12];
    const float* aWr_w    = (const float*)d_in[13];
    const float* aWr_b    = (const float*)d_in[14];
    const float* aUr_w    = (const float*)d_in[15];
    const float* aUr_b    = (const float*)d_in[16];
    const float* aW_w     = (const float*)d_in[17];
    const float* aW_b     = (const float*)d_in[18];
    const float* aU_w     = (const float*)d_in[19];
    const float* aU_b     = (const float*)d_in[20];
    const float* cls_w    = (const float*)d_in[21];
    const float* cls_b    = (const float*)d_in[22];
    float* out = (float*)d_out;

    float *gi_utt, *h_utt, *maxpool, *u, *inp0, *gi_ctx, *seq_ctx, *h_ctx;
    float *mem, *xr, *xw, *gates, *query, *h_att;
    cudaGetSymbolAddress((void**)&gi_utt,  g_gi_utt);
    cudaGetSymbolAddress((void**)&h_utt,   g_h_utt);
    cudaGetSymbolAddress((void**)&maxpool, g_maxpool);
    cudaGetSymbolAddress((void**)&u,       g_u);
    cudaGetSymbolAddress((void**)&inp0,    g_inp0);
    cudaGetSymbolAddress((void**)&gi_ctx,  g_gi_ctx);
    cudaGetSymbolAddress((void**)&seq_ctx, g_seq_ctx);
    cudaGetSymbolAddress((void**)&h_ctx,   g_h_ctx);
    cudaGetSymbolAddress((void**)&mem,     g_mem);
    cudaGetSymbolAddress((void**)&xr,      g_xr);
    cudaGetSymbolAddress((void**)&xw,      g_xw);
    cudaGetSymbolAddress((void**)&gates,   g_gates);
    cudaGetSymbolAddress((void**)&query,   g_query);
    cudaGetSymbolAddress((void**)&h_att,   g_h_att);

    float* hU0 = h_utt;                float* hU1 = h_utt + 2 * NB * HDIM;
    float* hC0 = h_ctx;                float* hC1 = h_ctx + 2 * NQ * HDIM;
    float* hA0 = h_att;                float* hA1 = h_att + 2 * NQ * HDIM;

    cudaStream_t s = 0;

    // ---- init h0 buffers ----
    fillk<<<(2 * NB * HDIM + 255) / 256, 256, 0, s>>>(hU0, 0.f, 2 * NB * HDIM);

    // ---- utterance GRU input projection (gathered emb) ----
    {
        dim3 g((1800 + GTN - 1) / GTN, (LSEQ * NB + GTM - 1) / GTM);
        gemm_kernel<1, 0><<<g, 256, 0, s>>>(nullptr, 0, utt_Wih, utt_bih,
                                            gi_utt, 1800, LSEQ * NB, 1800, EDIM, emb, ids);
    }
    // ---- utterance GRU scan (persistent, 64 steps) ----
    gru_scan_kernel<0><<<SCAN_BLOCKS, SCAN_THREADS, 0, s>>>(
        hU0, hU1, gi_utt, utt_Whh, utt_bhh, seq_lens, maxpool, nullptr, NB, LSEQ);

    // ---- u = tanh(maxpool @ lin_w^T + lin_b) ----
    {
        dim3 g((HDIM + GTN - 1) / GTN, (NB + GTM - 1) / GTM);
        gemm_kernel<0, 1><<<g, 256, 0, s>>>(maxpool, 2 * HDIM, lin_w, lin_b,
                                            u, HDIM, NB, HDIM, 2 * HDIM, nullptr, nullptr);
    }
    // ---- context windows + ctx GRU ----
    build_inp0<<<(KF * NQ * HDIM + 255) / 256, 256, 0, s>>>(u, inp0);
    fillk<<<(2 * NQ * HDIM + 255) / 256, 256, 0, s>>>(hC0, 0.f, 2 * NQ * HDIM);
    {
        dim3 g((1800 + GTN - 1) / GTN, (KF * NQ + GTM - 1) / GTM);
        gemm_kernel<0, 0><<<g, 256, 0, s>>>(inp0, HDIM, ctx_Wih, ctx_bih,
                                            gi_ctx, 1800, KF * NQ, 1800, HDIM, nullptr, nullptr);
    }
    gru_scan_kernel<1><<<SCAN_BLOCKS, SCAN_THREADS, 0, s>>>(
        hC0, hC1, gi_ctx, ctx_Whh, ctx_bhh, nullptr, nullptr, seq_ctx, NQ, KF);

    membank_kernel<<<(KF * NQ * HDIM + 255) / 256, 256, 0, s>>>(inp0, seq_ctx, mem);

    // ---- attention x-projections (hop-invariant; all hops/dirs in one GEMM each) ----
    {
        dim3 g((1800 + GTN - 1) / GTN, (KF * NQ + GTM - 1) / GTM);
        gemm_kernel<0, 0><<<g, 256, 0, s>>>(mem, HDIM, aWr_w, aWr_b,
                                            xr, 1800, KF * NQ, 1800, HDIM, nullptr, nullptr);
        gemm_kernel<0, 0><<<g, 256, 0, s>>>(mem, HDIM, aW_w, aW_b,
                                            xw, 1800, KF * NQ, 1800, HDIM, nullptr, nullptr);
    }

    // ---- query init + hops ----
    cudaMemcpyAsync(query, u + HDIM, NQ * HDIM * sizeof(float),
                    cudaMemcpyDeviceToDevice, s);
    for (int hop = 0; hop < NHOPS; hop++) {
        score_kernel<<<NQ, 128, 0, s>>>(query, mem, gates);
        fillk<<<(2 * NQ * HDIM + 255) / 256, 256, 0, s>>>(hA0, 0.f, 2 * NQ * HDIM);
        att_scan_kernel<<<SCAN_BLOCKS, SCAN_THREADS, 0, s>>>(
            hA0, hA1, xr, xw, aUr_w, aU_w, aUr_b, aU_b, gates, hop);
        // KF=40 steps: final state lands in hA0 (last write at t=39, odd -> h0)
        add2_kernel<<<(NQ * HDIM + 255) / 256, 256, 0, s>>>(
            query, hA0, hA0 + NQ * HDIM, NQ * HDIM);
    }

    // ---- classifier ----
    cls_kernel<<<NB, 192, 0, s>>>(u, query, cls_w, cls_b, out);
}

// round 8
// speedup vs baseline: 1.5003x; 1.5003x over previous
#include <cuda_runtime.h>
#include <math.h>

#define NB   128   // N dialogues
#define LSEQ 64    // L
#define EDIM 300
#define HDIM 300
#define KF   40    // KEFF
#define NQ   127   // N-1
#define NHOPS 3
#define NCLS 6

// ---------------- scratch (device globals; no allocation) ----------------
__device__ float g_gi_utt[(size_t)LSEQ * NB * 1800];     // [t*128+b, 1800]
__device__ float g_h_utt[2][2 * NB * HDIM];
__device__ float g_maxpool[NB * 2 * HDIM];
__device__ float g_u[NB * HDIM];
__device__ float g_inp0[KF * NQ * HDIM];                 // ctx_t time-major
__device__ float g_gi_ctx[(size_t)KF * NQ * 1800];
__device__ float g_seq_ctx[2 * KF * NQ * HDIM];          // [dir, t, i, j]
__device__ float g_h_ctx[2][2 * NQ * HDIM];
__device__ float g_mem[KF * NQ * HDIM];                  // time-major [k,i,j]
__device__ float g_xr[(size_t)KF * NQ * 1800];
__device__ float g_xw[(size_t)KF * NQ * 1800];
__device__ float g_gates[KF * NQ];
__device__ float g_query[NQ * HDIM];
__device__ float g_h_att[2][2 * NQ * HDIM];

__device__ __forceinline__ float sigf(float x) { return 1.f / (1.f + expf(-x)); }

// ---------------- generic GEMM: C = A(MxK) @ W(NxK)^T + bias ----------------
#define GTM 64
#define GTN 64
#define GTK 16

template<int GATHER, int EPI>
__global__ __launch_bounds__(256)
void gemm_kernel(const float* __restrict__ A, int lda,
                 const float* __restrict__ W,
                 const float* __restrict__ bias,
                 float* __restrict__ C, int ldc,
                 int M, int N, int K,
                 const float* __restrict__ emb,
                 const int* __restrict__ ids,
                 const int* __restrict__ seq_lens)
{
    __shared__ float As[GTK][GTM + 1];
    __shared__ float Bs[GTK][GTN + 1];
    __shared__ int   rowid[GTM];
    __shared__ int   smax;
    const int tid = threadIdx.x;
    const int m0 = blockIdx.y * GTM;
    const int n0 = blockIdx.x * GTN;

    if (GATHER) {
        // tile spans a single t (64-row tile inside a 128-row t-group)
        if (tid == 0) smax = 0;
        __syncthreads();
        if (tid < GTM) {
            int m = m0 + tid;
            int t = m >> 7, b = m & 127;          // m = t*128 + b
            rowid[tid] = (m < M) ? ids[b * LSEQ + t] : 0;
            atomicMax(&smax, seq_lens[b]);
        }
        __syncthreads();
        if ((m0 >> 7) >= smax) return;            // all-pad tile: rows never read
    }

    float acc[4][4] = {};
    const int mt = tid >> 4;   // 0..15
    const int nt = tid & 15;   // 0..15

    for (int k0 = 0; k0 < K; k0 += GTK) {
#pragma unroll
        for (int i = 0; i < 4; i++) {
            int idx = tid + i * 256;
            int mm = idx >> 4, kk = idx & 15;
            int m = m0 + mm, k = k0 + kk;
            float v = 0.f;
            if (m < M && k < K) {
                if (GATHER) v = emb[(size_t)rowid[mm] * K + k];
                else        v = A[(size_t)m * lda + k];
            }
            As[kk][mm] = v;
        }
#pragma unroll
        for (int i = 0; i < 4; i++) {
            int idx = tid + i * 256;
            int nn = idx >> 4, kk = idx & 15;
            int n = n0 + nn, k = k0 + kk;
            Bs[kk][nn] = (n < N && k < K) ? W[(size_t)n * K + k] : 0.f;
        }
        __syncthreads();
#pragma unroll
        for (int kk = 0; kk < GTK; kk++) {
            float a[4], b[4];
#pragma unroll
            for (int i = 0; i < 4; i++) a[i] = As[kk][mt * 4 + i];
#pragma unroll
            for (int j = 0; j < 4; j++) b[j] = Bs[kk][nt * 4 + j];
#pragma unroll
            for (int i = 0; i < 4; i++)
#pragma unroll
                for (int j = 0; j < 4; j++)
                    acc[i][j] += a[i] * b[j];
        }
        __syncthreads();
    }
#pragma unroll
    for (int i = 0; i < 4; i++) {
        int m = m0 + mt * 4 + i;
        if (m >= M) continue;
#pragma unroll
        for (int j = 0; j < 4; j++) {
            int n = n0 + nt * 4 + j;
            if (n >= N) continue;
            float v = acc[i][j] + bias[n];
            if (EPI == 1) v = tanhf(v);
            C[(size_t)m * ldc + n] = v;
        }
    }
}

// ---------------- GRU step v2: whole h + weight slice in smem ---------------
// Grid (30 jgrp, 2 bgrp, 2 dir), 160 threads. Thread: 1 unit x 4 batches x 3 gates.
// MODE 0: utt (mask + reversed gi row + maxpool RMW)
// MODE 1: ctx (full length, store seqout)
template<int MODE>
__global__ __launch_bounds__(160, 1)
void gru_step2(const float* __restrict__ hp, float* __restrict__ hn,
               const float* __restrict__ gi,      // [T*B, 1800]
               const float* __restrict__ Whh,     // [2,900,300]
               const float* __restrict__ bhh,     // [2,900]
               const int*   __restrict__ seq_lens,
               float* __restrict__ maxpool,       // [B, 600]
               float* __restrict__ seqout,        // [2,T,B,300]
               int t, int B, int T)
{
    extern __shared__ float sm[];
    float* Ws = sm;            // [3*10][300]
    float* Hs = sm + 9000;     // [64][300]
    const int tid  = threadIdx.x;
    const int jgrp = blockIdx.x, bgrp = blockIdx.y, dir = blockIdx.z;
    const int brow = tid & 15, u = tid >> 4;     // brow fastest -> smem broadcast
    const int j = jgrp * 10 + u;
    const int dirbase = dir * B * HDIM;
    const int b0 = bgrp * 64;

    // stage weights: 30 rows x 300 = 2250 float4
    for (int idx = tid; idx < 2250; idx += 160) {
        int row = idx / 75, q = idx % 75;
        int g = row / 10, uu = row % 10;
        ((float4*)Ws)[idx] =
            ((const float4*)(Whh + ((size_t)dir * 900 + g * 300 + jgrp * 10 + uu) * 300))[q];
    }
    // stage h: 64 x 300 = 4800 float4
    for (int idx = tid; idx < 4800; idx += 160) {
        int bl = idx / 75, q = idx % 75;
        int b = b0 + bl;
        float4 v = make_float4(0.f, 0.f, 0.f, 0.f);
        if (b < B) v = ((const float4*)(hp + dirbase + (size_t)b * 300))[q];
        ((float4*)Hs)[idx] = v;
    }

    // prefetch epilogue inputs (independent of h matvec)
    float gr0[4], gr1[4], gr2[4], hold[4], mpold[4];
    bool  msk[4], val[4];
#pragma unroll
    for (int i = 0; i < 4; i++) {
        int b = b0 + brow + 16 * i;
        val[i] = (b < B);
        int len = T; msk[i] = true;
        if (val[i]) {
            if (MODE == 0) { len = seq_lens[b]; msk[i] = (t < len); }
            int trow = (MODE == 0) ? ((dir == 0) ? t : max(len - 1 - t, 0))
                                   : ((dir == 0) ? t : (T - 1 - t));
            const float* gr = gi + ((size_t)trow * B + b) * 1800 + dir * 900 + j;
            gr0[i] = gr[0]; gr1[i] = gr[300]; gr2[i] = gr[600];
            hold[i] = hp[dirbase + (size_t)b * 300 + j];
            if (MODE == 0) mpold[i] = maxpool[b * (2 * HDIM) + dir * HDIM + j];
        }
    }
    const float bhr = bhh[dir * 900 + j];
    const float bhz = bhh[dir * 900 + 300 + j];
    const float bhn = bhh[dir * 900 + 600 + j];
    __syncthreads();

    float acc[4][3] = {};
    const float4* wr = (const float4*)(Ws + (0  + u) * 300);
    const float4* wz = (const float4*)(Ws + (10 + u) * 300);
    const float4* wn = (const float4*)(Ws + (20 + u) * 300);
#pragma unroll 5
    for (int q = 0; q < 75; q++) {
        float4 w0 = wr[q], w1 = wz[q], w2 = wn[q];
#pragma unroll
        for (int i = 0; i < 4; i++) {
            float4 h4 = ((const float4*)(Hs + (brow + 16 * i) * 300))[q];
            acc[i][0] += h4.x * w0.x + h4.y * w0.y + h4.z * w0.z + h4.w * w0.w;
            acc[i][1] += h4.x * w1.x + h4.y * w1.y + h4.z * w1.z + h4.w * w1.w;
            acc[i][2] += h4.x * w2.x + h4.y * w2.y + h4.z * w2.z + h4.w * w2.w;
        }
    }

#pragma unroll
    for (int i = 0; i < 4; i++) {
        if (!val[i]) continue;
        int b = b0 + brow + 16 * i;
        float r = sigf(gr0[i] + acc[i][0] + bhr);
        float z = sigf(gr1[i] + acc[i][1] + bhz);
        float n = tanhf(gr2[i] + r * (acc[i][2] + bhn));
        float hnew = (1.f - z) * n + z * hold[i];
        if (MODE == 0) {
            hn[dirbase + (size_t)b * 300 + j] = msk[i] ? hnew : hold[i];
            maxpool[b * (2 * HDIM) + dir * HDIM + j] =
                fmaxf(mpold[i], msk[i] ? hnew : 0.f);
        } else {
            hn[dirbase + (size_t)b * 300 + j] = hnew;
            seqout[(((size_t)dir * T + t) * B + b) * 300 + j] = hnew;
        }
    }
}

// ---------------- attention-GRU step v2 ----------------
__global__ __launch_bounds__(160, 1)
void att_step2(const float* __restrict__ hp, float* __restrict__ hn,
               const float* __restrict__ xr,   // [40*127, 1800]
               const float* __restrict__ xw,
               const float* __restrict__ Ur,   // [3,2,300,300]
               const float* __restrict__ Uw,
               const float* __restrict__ bur,  // [3,2,300]
               const float* __restrict__ bu,
               const float* __restrict__ gates, // [40*127]
               int t, int hop)
{
    extern __shared__ float sm[];
    float* Ws = sm;            // [2*10][300]
    float* Hs = sm + 6000;     // [64][300]
    const int tid  = threadIdx.x;
    const int jgrp = blockIdx.x, bgrp = blockIdx.y, dir = blockIdx.z;
    const int brow = tid & 15, u = tid >> 4;
    const int j = jgrp * 10 + u;
    const int wd = hop * 2 + dir;
    const int dirbase = dir * NQ * HDIM;
    const int b0 = bgrp * 64;

    for (int idx = tid; idx < 1500; idx += 160) {
        int row = idx / 75, q = idx % 75;
        int g = row / 10, uu = row % 10;
        const float* W = g ? Uw : Ur;
        ((float4*)Ws)[idx] =
            ((const float4*)(W + ((size_t)wd * 300 + jgrp * 10 + uu) * 300))[q];
    }
    for (int idx = tid; idx < 4800; idx += 160) {
        int bl = idx / 75, q = idx % 75;
        int b = b0 + bl;
        float4 v = make_float4(0.f, 0.f, 0.f, 0.f);
        if (b < NQ) v = ((const float4*)(hp + dirbase + (size_t)b * 300))[q];
        ((float4*)Hs)[idx] = v;
    }

    const int tt = (dir == 0) ? t : (KF - 1 - t);
    float xrv[4], xwv[4], gv[4], hold[4];
    bool  val[4];
#pragma unroll
    for (int i = 0; i < 4; i++) {
        int b = b0 + brow + 16 * i;
        val[i] = (b < NQ);
        if (val[i]) {
            size_t xrow = ((size_t)tt * NQ + b) * 1800 + wd * 300 + j;
            xrv[i] = xr[xrow]; xwv[i] = xw[xrow];
            gv[i]  = gates[tt * NQ + b];
            hold[i] = hp[dirbase + (size_t)b * 300 + j];
        }
    }
    const float burv = bur[wd * 300 + j];
    const float buv  = bu[wd * 300 + j];
    __syncthreads();

    float acc[4][2] = {};
    const float4* wrp = (const float4*)(Ws + u * 300);
    const float4* wwp = (const float4*)(Ws + (10 + u) * 300);
#pragma unroll 5
    for (int q = 0; q < 75; q++) {
        float4 w0 = wrp[q], w1 = wwp[q];
#pragma unroll
        for (int i = 0; i < 4; i++) {
            float4 h4 = ((const float4*)(Hs + (brow + 16 * i) * 300))[q];
            acc[i][0] += h4.x * w0.x + h4.y * w0.y + h4.z * w0.z + h4.w * w0.w;
            acc[i][1] += h4.x * w1.x + h4.y * w1.y + h4.z * w1.z + h4.w * w1.w;
        }
    }

#pragma unroll
    for (int i = 0; i < 4; i++) {
        if (!val[i]) continue;
        int b = b0 + brow + 16 * i;
        float r  = sigf(xrv[i] + acc[i][0] + burv);
        float ht = tanhf(xwv[i] + r * (acc[i][1] + buv));
        hn[dirbase + (size_t)b * 300 + j] = gv[i] * ht + (1.f - gv[i]) * hold[i];
    }
}

// ---------------- small kernels ----------------
__global__ void fillk(float* p, float v, int n) {
    int i = blockIdx.x * blockDim.x + threadIdx.x;
    if (i < n) p[i] = v;
}

// u = tanh(maxpool @ lin_w^T + lin_b); warp-per-output-column
__global__ __launch_bounds__(256)
void lin_kernel(const float* __restrict__ mp, const float* __restrict__ w,
                const float* __restrict__ bsc, float* __restrict__ u) {
    int b = blockIdx.x;
    __shared__ float m[600];
    for (int i = threadIdx.x; i < 600; i += 256) m[i] = mp[b * 600 + i];
    __syncthreads();
    int wid = threadIdx.x >> 5, lane = threadIdx.x & 31;
    for (int j = wid; j < HDIM; j += 8) {
        float acc = 0.f;
        const float* wr = w + (size_t)j * 600;
        for (int k = lane; k < 600; k += 32) acc += m[k] * wr[k];
        for (int o = 16; o > 0; o >>= 1) acc += __shfl_xor_sync(0xffffffffu, acc, o);
        if (lane == 0) u[b * HDIM + j] = tanhf(acc + bsc[j]);
    }
}

__global__ void build_inp0(const float* __restrict__ u, float* __restrict__ inp0) {
    int idx = blockIdx.x * blockDim.x + threadIdx.x;
    if (idx >= KF * NQ * HDIM) return;
    int j = idx % HDIM;
    int r = idx / HDIM;
    int i = r % NQ;
    int k = r / NQ;
    int src = (i + 1) - KF + k;
    inp0[idx] = (src >= 0) ? u[src * HDIM + j] : 0.f;
}

__global__ void membank_kernel(const float* __restrict__ inp0,
                               const float* __restrict__ seq,
                               float* __restrict__ mem) {
    int idx = blockIdx.x * blockDim.x + threadIdx.x;
    if (idx >= KF * NQ * HDIM) return;
    int j = idx % HDIM;
    int r = idx / HDIM;
    int i = r % NQ;
    int k = r / NQ;
    float f = seq[((size_t)k) * NQ * HDIM + i * HDIM + j];
    float b = seq[((size_t)KF + (KF - 1 - k)) * NQ * HDIM + i * HDIM + j];
    mem[idx] = inp0[idx] + f + b;
}

__global__ void score_kernel(const float* __restrict__ query,
                             const float* __restrict__ mem,
                             float* __restrict__ gates) {
    int b = blockIdx.x;                 // 0..126
    int tid = threadIdx.x;              // 128
    int lane = tid & 31, w = tid >> 5;
    __shared__ float q[HDIM];
    __shared__ float logit[KF];
    for (int i = tid; i < HDIM; i += 128) q[i] = query[b * HDIM + i];
    __syncthreads();
    for (int k = w; k < KF; k += 4) {
        const float* mrow = mem + ((size_t)k * NQ + b) * HDIM;
        float s = 0.f;
        for (int i = lane; i < HDIM; i += 32) s += q[i] * mrow[i];
        for (int o = 16; o > 0; o >>= 1) s += __shfl_xor_sync(0xffffffffu, s, o);
        if (lane == 0) logit[k] = (k >= KF - 1 - b) ? s : -1e10f;
    }
    __syncthreads();
    if (w == 0) {
        float m = -INFINITY;
        for (int k = lane; k < KF; k += 32) m = fmaxf(m, logit[k]);
        for (int o = 16; o > 0; o >>= 1) m = fmaxf(m, __shfl_xor_sync(0xffffffffu, m, o));
        float ssum = 0.f;
        for (int k = lane; k < KF; k += 32) { float e = expf(logit[k] - m); logit[k] = e; ssum += e; }
        for (int o = 16; o > 0; o >>= 1) ssum += __shfl_xor_sync(0xffffffffu, ssum, o);
        for (int k = lane; k < KF; k += 32) gates[k * NQ + b] = logit[k] / ssum;
    }
}

__global__ void add2_kernel(float* __restrict__ q,
                            const float* __restrict__ hf,
                            const float* __restrict__ hb, int n) {
    int i = blockIdx.x * blockDim.x + threadIdx.x;
    if (i < n) q[i] += hf[i] + hb[i];
}

__global__ void cls_kernel(const float* __restrict__ u,
                           const float* __restrict__ query,
                           const float* __restrict__ cls_w,
                           const float* __restrict__ cls_b,
                           float* __restrict__ out) {
    int row = blockIdx.x;               // 0..127
    int w = threadIdx.x >> 5, lane = threadIdx.x & 31;   // 192 threads = 6 warps
    const float* s = (row == 0) ? u : (query + (row - 1) * HDIM);
    float acc = 0.f;
    for (int i = lane; i < HDIM; i += 32) acc += s[i] * cls_w[w * HDIM + i];
    for (int o = 16; o > 0; o >>= 1) acc += __shfl_xor_sync(0xffffffffu, acc, o);
    if (lane == 0) out[row * NCLS + w] = acc + cls_b[w];
}

// ---------------- host orchestration ----------------
extern "C" void kernel_launch(void* const* d_in, const int* in_sizes, int n_in,
                              void* d_out, int out_size) {
    const int*   ids      = (const int*)d_in[0];
    const int*   seq_lens = (const int*)d_in[1];
    const float* emb      = (const float*)d_in[2];
    const float* utt_Wih  = (const float*)d_in[3];
    const float* utt_Whh  = (const float*)d_in[4];
    const float* utt_bih  = (const float*)d_in[5];
    const float* utt_bhh  = (const float*)d_in[6];
    const float* lin_w    = (const float*)d_in[7];
    const float* lin_b    = (const float*)d_in[8];
    const float* ctx_Wih  = (const float*)d_in[9];
    const float* ctx_Whh  = (const float*)d_in[10];
    const float* ctx_bih  = (const float*)d_in[11];
    const float* ctx_bhh  = (const float*)d_in[12];
    const float* aWr_w    = (const float*)d_in[13];
    const float* aWr_b    = (const float*)d_in[14];
    const float* aUr_w    = (const float*)d_in[15];
    const float* aUr_b    = (const float*)d_in[16];
    const float* aW_w     = (const float*)d_in[17];
    const float* aW_b     = (const float*)d_in[18];
    const float* aU_w     = (const float*)d_in[19];
    const float* aU_b     = (const float*)d_in[20];
    const float* cls_w    = (const float*)d_in[21];
    const float* cls_b    = (const float*)d_in[22];
    float* out = (float*)d_out;

    float *gi_utt, *h_utt, *maxpool, *u, *inp0, *gi_ctx, *seq_ctx, *h_ctx;
    float *mem, *xr, *xw, *gates, *query, *h_att;
    cudaGetSymbolAddress((void**)&gi_utt,  g_gi_utt);
    cudaGetSymbolAddress((void**)&h_utt,   g_h_utt);
    cudaGetSymbolAddress((void**)&maxpool, g_maxpool);
    cudaGetSymbolAddress((void**)&u,       g_u);
    cudaGetSymbolAddress((void**)&inp0,    g_inp0);
    cudaGetSymbolAddress((void**)&gi_ctx,  g_gi_ctx);
    cudaGetSymbolAddress((void**)&seq_ctx, g_seq_ctx);
    cudaGetSymbolAddress((void**)&h_ctx,   g_h_ctx);
    cudaGetSymbolAddress((void**)&mem,     g_mem);
    cudaGetSymbolAddress((void**)&xr,      g_xr);
    cudaGetSymbolAddress((void**)&xw,      g_xw);
    cudaGetSymbolAddress((void**)&gates,   g_gates);
    cudaGetSymbolAddress((void**)&query,   g_query);
    cudaGetSymbolAddress((void**)&h_att,   g_h_att);

    float* hU0 = h_utt;  float* hU1 = h_utt + 2 * NB * HDIM;
    float* hC0 = h_ctx;  float* hC1 = h_ctx + 2 * NQ * HDIM;
    float* hA0 = h_att;  float* hA1 = h_att + 2 * NQ * HDIM;

    const int GRU_SMEM = (9000 + 64 * 300) * 4;   // 112800
    const int ATT_SMEM = (6000 + 64 * 300) * 4;   // 100800
    cudaFuncSetAttribute(gru_step2<0>, cudaFuncAttributeMaxDynamicSharedMemorySize, GRU_SMEM);
    cudaFuncSetAttribute(gru_step2<1>, cudaFuncAttributeMaxDynamicSharedMemorySize, GRU_SMEM);
    cudaFuncSetAttribute(att_step2,    cudaFuncAttributeMaxDynamicSharedMemorySize, ATT_SMEM);

    cudaStream_t s = 0;

    // ---- init ----
    fillk<<<(NB * 2 * HDIM + 255) / 256, 256, 0, s>>>(maxpool, -1e30f, NB * 2 * HDIM);
    fillk<<<(2 * NB * HDIM + 255) / 256, 256, 0, s>>>(hU0, 0.f, 2 * NB * HDIM);

    // ---- utterance GRU input projection (gathered emb, pad-skip) ----
    {
        dim3 g((1800 + GTN - 1) / GTN, (LSEQ * NB + GTM - 1) / GTM);
        gemm_kernel<1, 0><<<g, 256, 0, s>>>(nullptr, 0, utt_Wih, utt_bih,
                                            gi_utt, 1800, LSEQ * NB, 1800, EDIM,
                                            emb, ids, seq_lens);
    }
    // ---- utterance GRU scan (64 per-step launches) ----
    {
        dim3 g(30, 2, 2);
        int cur = 0;
        for (int t = 0; t < LSEQ; t++) {
            gru_step2<0><<<g, 160, GRU_SMEM, s>>>(cur ? hU1 : hU0, cur ? hU0 : hU1,
                                                  gi_utt, utt_Whh, utt_bhh, seq_lens,
                                                  maxpool, nullptr, t, NB, LSEQ);
            cur ^= 1;
        }
    }
    // ---- u = tanh(maxpool @ lin_w^T + lin_b) ----
    lin_kernel<<<NB, 256, 0, s>>>(maxpool, lin_w, lin_b, u);

    // ---- context windows + ctx GRU ----
    build_inp0<<<(KF * NQ * HDIM + 255) / 256, 256, 0, s>>>(u, inp0);
    fillk<<<(2 * NQ * HDIM + 255) / 256, 256, 0, s>>>(hC0, 0.f, 2 * NQ * HDIM);
    {
        dim3 g((1800 + GTN - 1) / GTN, (KF * NQ + GTM - 1) / GTM);
        gemm_kernel<0, 0><<<g, 256, 0, s>>>(inp0, HDIM, ctx_Wih, ctx_bih,
                                            gi_ctx, 1800, KF * NQ, 1800, HDIM,
                                            nullptr, nullptr, nullptr);
    }
    {
        dim3 g(30, 2, 2);
        int cur = 0;
        for (int t = 0; t < KF; t++) {
            gru_step2<1><<<g, 160, GRU_SMEM, s>>>(cur ? hC1 : hC0, cur ? hC0 : hC1,
                                                  gi_ctx, ctx_Whh, ctx_bhh, nullptr,
                                                  nullptr, seq_ctx, t, NQ, KF);
            cur ^= 1;
        }
    }
    membank_kernel<<<(KF * NQ * HDIM + 255) / 256, 256, 0, s>>>(inp0, seq_ctx, mem);

    // ---- attention x-projections (hop-invariant; one GEMM each) ----
    {
        dim3 g((1800 + GTN - 1) / GTN, (KF * NQ + GTM - 1) / GTM);
        gemm_kernel<0, 0><<<g, 256, 0, s>>>(mem, HDIM, aWr_w, aWr_b,
                                            xr, 1800, KF * NQ, 1800, HDIM,
                                            nullptr, nullptr, nullptr);
        gemm_kernel<0, 0><<<g, 256, 0, s>>>(mem, HDIM, aW_w, aW_b,
                                            xw, 1800, KF * NQ, 1800, HDIM,
                                            nullptr, nullptr, nullptr);
    }

    // ---- query init + hops ----
    cudaMemcpyAsync(query, u + HDIM, NQ * HDIM * sizeof(float),
                    cudaMemcpyDeviceToDevice, s);
    dim3 ga(30, 2, 2);
    for (int hop = 0; hop < NHOPS; hop++) {
        score_kernel<<<NQ, 128, 0, s>>>(query, mem, gates);
        fillk<<<(2 * NQ * HDIM + 255) / 256, 256, 0, s>>>(hA0, 0.f, 2 * NQ * HDIM);
        int cur = 0;
        for (int t = 0; t < KF; t++) {
            att_step2<<<ga, 160, ATT_SMEM, s>>>(cur ? hA1 : hA0, cur ? hA0 : hA1,
                                                xr, xw, aUr_w, aU_w, aUr_b, aU_b,
                                                gates, t, hop);
            cur ^= 1;
        }
        // KF=40 even: final state in hA0
        add2_kernel<<<(NQ * HDIM + 255) / 256, 256, 0, s>>>(
            query, hA0, hA0 + NQ * HDIM, NQ * HDIM);
    }

    // ---- classifier ----
    cls_kernel<<<NB, 192, 0, s>>>(u, query, cls_w, cls_b, out);
}

// round 9
// speedup vs baseline: 2.0845x; 1.3893x over previous
#include <cuda_runtime.h>
#include <math.h>

#define NB   128   // N dialogues
#define LSEQ 64    // L
#define EDIM 300
#define HDIM 300
#define KF   40    // KEFF
#define NQ   127   // N-1
#define NHOPS 3
#define NCLS 6

typedef unsigned long long u64;

// ---------------- scratch (device globals; no allocation) ----------------
__device__ float g_gi_utt[(size_t)LSEQ * NB * 1800];     // [t*128+b, 1800]
__device__ float g_h_utt[2][2 * NB * HDIM];
__device__ float g_maxpool[NB * 2 * HDIM];
__device__ float g_u[NB * HDIM];
__device__ float g_inp0[KF * NQ * HDIM];                 // ctx_t time-major
__device__ float g_gi_ctx[(size_t)KF * NQ * 1800];
__device__ float g_seq_ctx[2 * KF * NQ * HDIM];          // [dir, t, i, j]
__device__ float g_h_ctx[2][2 * NQ * HDIM];
__device__ float g_mem[KF * NQ * HDIM];                  // time-major [k,i,j]
__device__ float g_xr[(size_t)KF * NQ * 1800];
__device__ float g_xw[(size_t)KF * NQ * 1800];
__device__ float g_gates[KF * NQ];
__device__ float g_query[NQ * HDIM];
__device__ float g_h_att[2][2 * NQ * HDIM];

__device__ __forceinline__ float sigf(float x) { return 1.f / (1.f + expf(-x)); }

// ---------------- packed f32x2 helpers ----------------
__device__ __forceinline__ u64 pk2(float x, float y) {
    u64 r; asm("mov.b64 %0, {%1, %2};" : "=l"(r) : "f"(x), "f"(y)); return r;
}
__device__ __forceinline__ float2 unpk(u64 v) {
    float2 f; asm("mov.b64 {%0, %1}, %2;" : "=f"(f.x), "=f"(f.y) : "l"(v)); return f;
}
__device__ __forceinline__ u64 f2fma(u64 a, u64 b, u64 c) {
    u64 d; asm("fma.rn.f32x2 %0, %1, %2, %3;" : "=l"(d) : "l"(a), "l"(b), "l"(c));
    return d;
}

// ---------------- GEMM v3 (f32x2): C = A(MxK) @ W(NxK)^T + bias ----------------
#define GTM 64
#define GTN 64
#define GTK 16

template<int GATHER>
__global__ __launch_bounds__(256)
void gemm3(const float* __restrict__ A, int lda,
           const float* __restrict__ W,
           const float* __restrict__ bias,
           float* __restrict__ C, int ldc,
           int M, int N, int K,
           const float* __restrict__ emb,
           const int* __restrict__ ids)
{
    __shared__ __align__(16) u64   Ad[GTK][66];   // A dup'd: (a,a) per [kk][mm]
    __shared__ __align__(16) float Bs[GTK][66];
    __shared__ int rowid[GTM];
    const int tid = threadIdx.x;
    const int m0 = blockIdx.y * GTM;
    const int n0 = blockIdx.x * GTN;

    if (GATHER) {
        if (tid < GTM) {
            int m = m0 + tid;
            int t = m >> 7, b = m & 127;          // m = t*128 + b
            rowid[tid] = (m < M) ? ids[b * LSEQ + t] : 0;
        }
        __syncthreads();
    }

    u64 acc[4][2] = {};
    const int mt = tid >> 4;   // 0..15
    const int nt = tid & 15;   // 0..15

    for (int k0 = 0; k0 < K; k0 += GTK) {
#pragma unroll
        for (int i = 0; i < 4; i++) {
            int idx = tid + i * 256;
            int mm = idx >> 4, kk = idx & 15;
            int m = m0 + mm, k = k0 + kk;
            float v = 0.f;
            if (m < M && k < K) {
                if (GATHER) v = emb[(size_t)rowid[mm] * K + k];
                else        v = A[(size_t)m * lda + k];
            }
            Ad[kk][mm] = pk2(v, v);
        }
#pragma unroll
        for (int i = 0; i < 4; i++) {
            int idx = tid + i * 256;
            int nn = idx >> 4, kk = idx & 15;
            int n = n0 + nn, k = k0 + kk;
            Bs[kk][nn] = (n < N && k < K) ? W[(size_t)n * K + k] : 0.f;
        }
        __syncthreads();
#pragma unroll
        for (int kk = 0; kk < GTK; kk++) {
            ulonglong2 a01 = *(const ulonglong2*)&Ad[kk][mt * 4];
            ulonglong2 a23 = *(const ulonglong2*)&Ad[kk][mt * 4 + 2];
            u64 b0 = *(const u64*)&Bs[kk][nt * 4];
            u64 b1 = *(const u64*)&Bs[kk][nt * 4 + 2];
            acc[0][0] = f2fma(a01.x, b0, acc[0][0]);
            acc[0][1] = f2fma(a01.x, b1, acc[0][1]);
            acc[1][0] = f2fma(a01.y, b0, acc[1][0]);
            acc[1][1] = f2fma(a01.y, b1, acc[1][1]);
            acc[2][0] = f2fma(a23.x, b0, acc[2][0]);
            acc[2][1] = f2fma(a23.x, b1, acc[2][1]);
            acc[3][0] = f2fma(a23.y, b0, acc[3][0]);
            acc[3][1] = f2fma(a23.y, b1, acc[3][1]);
        }
        __syncthreads();
    }
#pragma unroll
    for (int i = 0; i < 4; i++) {
        int m = m0 + mt * 4 + i;
        if (m >= M) continue;
#pragma unroll
        for (int p = 0; p < 2; p++) {
            float2 v = unpk(acc[i][p]);
            int n = n0 + nt * 4 + 2 * p;
            if (n < N)     C[(size_t)m * ldc + n]     = v.x + bias[n];
            if (n + 1 < N) C[(size_t)m * ldc + n + 1] = v.y + bias[n + 1];
        }
    }
}

// ---------------- GRU step v3 (f32x2, 320 threads) ----------------
// Grid (30 jgrp, 2 bgrp, 2 dir). Thread: unit j, batch pair (b, b+32), 3 gates.
// Smem: Wd = dup'd weights [30 rows][300] u64; Hs4 = h pairs [150 k2][32] float4
//       where Hs4[k2][p] = (h[blo][2k2], h[bhi][2k2], h[blo][2k2+1], h[bhi][2k2+1])
// MODE 0: utt (mask + reversed gi + maxpool, t==0 init) | MODE 1: ctx (seqout)
template<int MODE>
__global__ __launch_bounds__(320, 1)
void gru_step3(const float* __restrict__ hp, float* __restrict__ hn,
               const float* __restrict__ gi,      // [T*B, 1800]
               const float* __restrict__ Whh,     // [2,900,300]
               const float* __restrict__ bhh,     // [2,900]
               const int*   __restrict__ seq_lens,
               float* __restrict__ maxpool,       // [B, 600]
               float* __restrict__ seqout,        // [2,T,B,300]
               int t, int B, int T)
{
    extern __shared__ float sm[];
    u64*    Wd  = (u64*)sm;                 // 9000 u64 = 72000 B
    float4* Hs4 = (float4*)(sm + 18000);    // 4800 float4 = 76800 B

    const int tid  = threadIdx.x;
    const int jgrp = blockIdx.x, bgrp = blockIdx.y, dir = blockIdx.z;
    const int brow = tid & 31, uu = tid >> 5;   // uu 0..9
    const int j = jgrp * 10 + uu;
    const int dirbase = dir * B * HDIM;
    const int b0 = bgrp * 64;
    const int b_lo = b0 + brow, b_hi = b_lo + 32;

    if (t > 0) {
        // stage dup'd weights: 30 rows x 75 float4
        for (int idx = tid; idx < 2250; idx += 320) {
            int row = idx / 75, q = idx % 75;
            int g = row / 10, ju = row % 10;
            float4 w = ((const float4*)(Whh +
                ((size_t)dir * 900 + g * 300 + jgrp * 10 + ju) * 300))[q];
            u64* dst = Wd + (size_t)row * 300 + q * 4;
            dst[0] = pk2(w.x, w.x); dst[1] = pk2(w.y, w.y);
            dst[2] = pk2(w.z, w.z); dst[3] = pk2(w.w, w.w);
        }
        // stage h pairs: tasks p(0..31) x kq(0..74)
        for (int idx = tid; idx < 2400; idx += 320) {
            int kq = idx >> 5, p = idx & 31;
            int blo = b0 + p, bhi = blo + 32;
            float4 lo = make_float4(0.f, 0.f, 0.f, 0.f), hi = lo;
            if (blo < B) lo = ((const float4*)(hp + dirbase + (size_t)blo * 300))[kq];
            if (bhi < B) hi = ((const float4*)(hp + dirbase + (size_t)bhi * 300))[kq];
            Hs4[(2 * kq)     * 32 + p] = make_float4(lo.x, hi.x, lo.y, hi.y);
            Hs4[(2 * kq + 1) * 32 + p] = make_float4(lo.z, hi.z, lo.w, hi.w);
        }
    }

    // epilogue prefetch (global only; overlaps staging)
    float grA[3], grB[3], holdA = 0.f, holdB = 0.f, mpA = -1e30f, mpB = -1e30f;
    bool mA = true, mB = true;
    int lenA = T, lenB = T;
    {
        if (b_lo < B) {
            if (MODE == 0) { lenA = seq_lens[b_lo]; mA = (t < lenA); }
            int trow = (MODE == 0) ? ((dir == 0) ? t : max(lenA - 1 - t, 0))
                                   : ((dir == 0) ? t : (T - 1 - t));
            const float* gr = gi + ((size_t)trow * B + b_lo) * 1800 + dir * 900 + j;
            grA[0] = gr[0]; grA[1] = gr[300]; grA[2] = gr[600];
            if (t > 0) holdA = hp[dirbase + (size_t)b_lo * 300 + j];
            if (MODE == 0 && t > 0) mpA = maxpool[b_lo * (2 * HDIM) + dir * HDIM + j];
        }
        if (b_hi < B) {
            if (MODE == 0) { lenB = seq_lens[b_hi]; mB = (t < lenB); }
            int trow = (MODE == 0) ? ((dir == 0) ? t : max(lenB - 1 - t, 0))
                                   : ((dir == 0) ? t : (T - 1 - t));
            const float* gr = gi + ((size_t)trow * B + b_hi) * 1800 + dir * 900 + j;
            grB[0] = gr[0]; grB[1] = gr[300]; grB[2] = gr[600];
            if (t > 0) holdB = hp[dirbase + (size_t)b_hi * 300 + j];
            if (MODE == 0 && t > 0) mpB = maxpool[b_hi * (2 * HDIM) + dir * HDIM + j];
        }
    }
    const float bhr = bhh[dir * 900 + j];
    const float bhz = bhh[dir * 900 + 300 + j];
    const float bhn = bhh[dir * 900 + 600 + j];
    __syncthreads();

    u64 ar = 0ULL, az = 0ULL, an = 0ULL;
    if (t > 0) {
        const ulonglong2* wr = (const ulonglong2*)(Wd + (size_t)(0  + uu) * 300);
        const ulonglong2* wz = (const ulonglong2*)(Wd + (size_t)(10 + uu) * 300);
        const ulonglong2* wn = (const ulonglong2*)(Wd + (size_t)(20 + uu) * 300);
        const ulonglong2* hs = (const ulonglong2*)Hs4 + brow;
#pragma unroll 6
        for (int k2 = 0; k2 < 150; k2++) {
            ulonglong2 h  = hs[k2 << 5];
            ulonglong2 w0 = wr[k2], w1 = wz[k2], w2 = wn[k2];
            ar = f2fma(h.x, w0.x, ar); ar = f2fma(h.y, w0.y, ar);
            az = f2fma(h.x, w1.x, az); az = f2fma(h.y, w1.y, az);
            an = f2fma(h.x, w2.x, an); an = f2fma(h.y, w2.y, an);
        }
    }
    float2 fr = unpk(ar), fz = unpk(az), fn = unpk(an);

    // half A (b_lo)
    if (b_lo < B) {
        float r = sigf(grA[0] + fr.x + bhr);
        float z = sigf(grA[1] + fz.x + bhz);
        float n = tanhf(grA[2] + r * (fn.x + bhn));
        float hnew = (1.f - z) * n + z * holdA;
        if (MODE == 0) {
            hn[dirbase + (size_t)b_lo * 300 + j] = mA ? hnew : holdA;
            maxpool[b_lo * (2 * HDIM) + dir * HDIM + j] = fmaxf(mpA, mA ? hnew : 0.f);
        } else {
            hn[dirbase + (size_t)b_lo * 300 + j] = hnew;
            seqout[(((size_t)dir * T + t) * B + b_lo) * 300 + j] = hnew;
        }
    }
    // half B (b_hi)
    if (b_hi < B) {
        float r = sigf(grB[0] + fr.y + bhr);
        float z = sigf(grB[1] + fz.y + bhz);
        float n = tanhf(grB[2] + r * (fn.y + bhn));
        float hnew = (1.f - z) * n + z * holdB;
        if (MODE == 0) {
            hn[dirbase + (size_t)b_hi * 300 + j] = mB ? hnew : holdB;
            maxpool[b_hi * (2 * HDIM) + dir * HDIM + j] = fmaxf(mpB, mB ? hnew : 0.f);
        } else {
            hn[dirbase + (size_t)b_hi * 300 + j] = hnew;
            seqout[(((size_t)dir * T + t) * B + b_hi) * 300 + j] = hnew;
        }
    }
}

// ---------------- attention-GRU step v3 (f32x2, 320 threads) ----------------
__global__ __launch_bounds__(320, 1)
void att_step3(const float* __restrict__ hp, float* __restrict__ hn,
               const float* __restrict__ xr,   // [40*127, 1800]
               const float* __restrict__ xw,
               const float* __restrict__ Ur,   // [3,2,300,300]
               const float* __restrict__ Uw,
               const float* __restrict__ bur,  // [3,2,300]
               const float* __restrict__ bu,
               const float* __restrict__ gates, // [40*127]
               int t, int hop)
{
    extern __shared__ float sm[];
    u64*    Wd  = (u64*)sm;                 // 6000 u64 = 48000 B
    float4* Hs4 = (float4*)(sm + 12000);    // 4800 float4

    const int tid  = threadIdx.x;
    const int jgrp = blockIdx.x, bgrp = blockIdx.y, dir = blockIdx.z;
    const int brow = tid & 31, uu = tid >> 5;
    const int j = jgrp * 10 + uu;
    const int wd = hop * 2 + dir;
    const int dirbase = dir * NQ * HDIM;
    const int b0 = bgrp * 64;
    const int b_lo = b0 + brow, b_hi = b_lo + 32;

    if (t > 0) {
        for (int idx = tid; idx < 1500; idx += 320) {
            int row = idx / 75, q = idx % 75;
            int g = row / 10, ju = row % 10;
            const float* Wsrc = g ? Uw : Ur;
            float4 w = ((const float4*)(Wsrc +
                ((size_t)wd * 300 + jgrp * 10 + ju) * 300))[q];
            u64* dst = Wd + (size_t)row * 300 + q * 4;
            dst[0] = pk2(w.x, w.x); dst[1] = pk2(w.y, w.y);
            dst[2] = pk2(w.z, w.z); dst[3] = pk2(w.w, w.w);
        }
        for (int idx = tid; idx < 2400; idx += 320) {
            int kq = idx >> 5, p = idx & 31;
            int blo = b0 + p, bhi = blo + 32;
            float4 lo = make_float4(0.f, 0.f, 0.f, 0.f), hi = lo;
            if (blo < NQ) lo = ((const float4*)(hp + dirbase + (size_t)blo * 300))[kq];
            if (bhi < NQ) hi = ((const float4*)(hp + dirbase + (size_t)bhi * 300))[kq];
            Hs4[(2 * kq)     * 32 + p] = make_float4(lo.x, hi.x, lo.y, hi.y);
            Hs4[(2 * kq + 1) * 32 + p] = make_float4(lo.z, hi.z, lo.w, hi.w);
        }
    }

    const int tt = (dir == 0) ? t : (KF - 1 - t);
    float xrA = 0.f, xwA = 0.f, gA = 0.f, holdA = 0.f;
    float xrB = 0.f, xwB = 0.f, gB = 0.f, holdB = 0.f;
    if (b_lo < NQ) {
        size_t xrow = ((size_t)tt * NQ + b_lo) * 1800 + wd * 300 + j;
        xrA = xr[xrow]; xwA = xw[xrow]; gA = gates[tt * NQ + b_lo];
        if (t > 0) holdA = hp[dirbase + (size_t)b_lo * 300 + j];
    }
    if (b_hi < NQ) {
        size_t xrow = ((size_t)tt * NQ + b_hi) * 1800 + wd * 300 + j;
        xrB = xr[xrow]; xwB = xw[xrow]; gB = gates[tt * NQ + b_hi];
        if (t > 0) holdB = hp[dirbase + (size_t)b_hi * 300 + j];
    }
    const float burv = bur[wd * 300 + j];
    const float buv  = bu[wd * 300 + j];
    __syncthreads();

    u64 ar = 0ULL, aw = 0ULL;
    if (t > 0) {
        const ulonglong2* wrp = (const ulonglong2*)(Wd + (size_t)uu * 300);
        const ulonglong2* wwp = (const ulonglong2*)(Wd + (size_t)(10 + uu) * 300);
        const ulonglong2* hs  = (const ulonglong2*)Hs4 + brow;
#pragma unroll 6
        for (int k2 = 0; k2 < 150; k2++) {
            ulonglong2 h  = hs[k2 << 5];
            ulonglong2 w0 = wrp[k2], w1 = wwp[k2];
            ar = f2fma(h.x, w0.x, ar); ar = f2fma(h.y, w0.y, ar);
            aw = f2fma(h.x, w1.x, aw); aw = f2fma(h.y, w1.y, aw);
        }
    }
    float2 fr = unpk(ar), fw = unpk(aw);

    if (b_lo < NQ) {
        float r  = sigf(xrA + fr.x + burv);
        float ht = tanhf(xwA + r * (fw.x + buv));
        hn[dirbase + (size_t)b_lo * 300 + j] = gA * ht + (1.f - gA) * holdA;
    }
    if (b_hi < NQ) {
        float r  = sigf(xrB + fr.y + burv);
        float ht = tanhf(xwB + r * (fw.y + buv));
        hn[dirbase + (size_t)b_hi * 300 + j] = gB * ht + (1.f - gB) * holdB;
    }
}

// ---------------- small kernels ----------------
// u = tanh(maxpool @ lin_w^T + lin_b); warp-per-output-column
__global__ __launch_bounds__(256)
void lin_kernel(const float* __restrict__ mp, const float* __restrict__ w,
                const float* __restrict__ bsc, float* __restrict__ u) {
    int b = blockIdx.x;
    __shared__ float m[600];
    for (int i = threadIdx.x; i < 600; i += 256) m[i] = mp[b * 600 + i];
    __syncthreads();
    int wid = threadIdx.x >> 5, lane = threadIdx.x & 31;
    for (int j = wid; j < HDIM; j += 8) {
        float acc = 0.f;
        const float* wr = w + (size_t)j * 600;
        for (int k = lane; k < 600; k += 32) acc += m[k] * wr[k];
        for (int o = 16; o > 0; o >>= 1) acc += __shfl_xor_sync(0xffffffffu, acc, o);
        if (lane == 0) u[b * HDIM + j] = tanhf(acc + bsc[j]);
    }
}

__global__ void build_inp0(const float* __restrict__ u, float* __restrict__ inp0) {
    int idx = blockIdx.x * blockDim.x + threadIdx.x;
    if (idx >= KF * NQ * HDIM) return;
    int j = idx % HDIM;
    int r = idx / HDIM;
    int i = r % NQ;
    int k = r / NQ;
    int src = (i + 1) - KF + k;
    inp0[idx] = (src >= 0) ? u[src * HDIM + j] : 0.f;
}

__global__ void membank_kernel(const float* __restrict__ inp0,
                               const float* __restrict__ seq,
                               float* __restrict__ mem) {
    int idx = blockIdx.x * blockDim.x + threadIdx.x;
    if (idx >= KF * NQ * HDIM) return;
    int j = idx % HDIM;
    int r = idx / HDIM;
    int i = r % NQ;
    int k = r / NQ;
    float f = seq[((size_t)k) * NQ * HDIM + i * HDIM + j];
    float b = seq[((size_t)KF + (KF - 1 - k)) * NQ * HDIM + i * HDIM + j];
    mem[idx] = inp0[idx] + f + b;
}

__global__ void score_kernel(const float* __restrict__ query,
                             const float* __restrict__ mem,
                             float* __restrict__ gates) {
    int b = blockIdx.x;                 // 0..126
    int tid = threadIdx.x;              // 128
    int lane = tid & 31, w = tid >> 5;
    __shared__ float q[HDIM];
    __shared__ float logit[KF];
    for (int i = tid; i < HDIM; i += 128) q[i] = query[b * HDIM + i];
    __syncthreads();
    for (int k = w; k < KF; k += 4) {
        const float* mrow = mem + ((size_t)k * NQ + b) * HDIM;
        float s = 0.f;
        for (int i = lane; i < HDIM; i += 32) s += q[i] * mrow[i];
        for (int o = 16; o > 0; o >>= 1) s += __shfl_xor_sync(0xffffffffu, s, o);
        if (lane == 0) logit[k] = (k >= KF - 1 - b) ? s : -1e10f;
    }
    __syncthreads();
    if (w == 0) {
        float m = -INFINITY;
        for (int k = lane; k < KF; k += 32) m = fmaxf(m, logit[k]);
        for (int o = 16; o > 0; o >>= 1) m = fmaxf(m, __shfl_xor_sync(0xffffffffu, m, o));
        float ssum = 0.f;
        for (int k = lane; k < KF; k += 32) { float e = expf(logit[k] - m); logit[k] = e; ssum += e; }
        for (int o = 16; o > 0; o >>= 1) ssum += __shfl_xor_sync(0xffffffffu, ssum, o);
        for (int k = lane; k < KF; k += 32) gates[k * NQ + b] = logit[k] / ssum;
    }
}

__global__ void add2_kernel(float* __restrict__ q,
                            const float* __restrict__ hf,
                            const float* __restrict__ hb, int n) {
    int i = blockIdx.x * blockDim.x + threadIdx.x;
    if (i < n) q[i] += hf[i] + hb[i];
}

__global__ void cls_kernel(const float* __restrict__ u,
                           const float* __restrict__ query,
                           const float* __restrict__ cls_w,
                           const float* __restrict__ cls_b,
                           float* __restrict__ out) {
    int row = blockIdx.x;               // 0..127
    int w = threadIdx.x >> 5, lane = threadIdx.x & 31;   // 192 threads = 6 warps
    const float* s = (row == 0) ? u : (query + (row - 1) * HDIM);
    float acc = 0.f;
    for (int i = lane; i < HDIM; i += 32) acc += s[i] * cls_w[w * HDIM + i];
    for (int o = 16; o > 0; o >>= 1) acc += __shfl_xor_sync(0xffffffffu, acc, o);
    if (lane == 0) out[row * NCLS + w] = acc + cls_b[w];
}

// ---------------- host orchestration ----------------
extern "C" void kernel_launch(void* const* d_in, const int* in_sizes, int n_in,
                              void* d_out, int out_size) {
    const int*   ids      = (const int*)d_in[0];
    const int*   seq_lens = (const int*)d_in[1];
    const float* emb      = (const float*)d_in[2];
    const float* utt_Wih  = (const float*)d_in[3];
    const float* utt_Whh  = (const float*)d_in[4];
    const float* utt_bih  = (const float*)d_in[5];
    const float* utt_bhh  = (const float*)d_in[6];
    const float* lin_w    = (const float*)d_in[7];
    const float* lin_b    = (const float*)d_in[8];
    const float* ctx_Wih  = (const float*)d_in[9];
    const float* ctx_Whh  = (const float*)d_in[10];
    const float* ctx_bih  = (const float*)d_in[11];
    const float* ctx_bhh  = (const float*)d_in[12];
    const float* aWr_w    = (const float*)d_in[13];
    const float* aWr_b    = (const float*)d_in[14];
    const float* aUr_w    = (const float*)d_in[15];
    const float* aUr_b    = (const float*)d_in[16];
    const float* aW_w     = (const float*)d_in[17];
    const float* aW_b     = (const float*)d_in[18];
    const float* aU_w     = (const float*)d_in[19];
    const float* aU_b     = (const float*)d_in[20];
    const float* cls_w    = (const float*)d_in[21];
    const float* cls_b    = (const float*)d_in[22];
    float* out = (float*)d_out;

    float *gi_utt, *h_utt, *maxpool, *u, *inp0, *gi_ctx, *seq_ctx, *h_ctx;
    float *mem, *xr, *xw, *gates, *query, *h_att;
    cudaGetSymbolAddress((void**)&gi_utt,  g_gi_utt);
    cudaGetSymbolAddress((void**)&h_utt,   g_h_utt);
    cudaGetSymbolAddress((void**)&maxpool, g_maxpool);
    cudaGetSymbolAddress((void**)&u,       g_u);
    cudaGetSymbolAddress((void**)&inp0,    g_inp0);
    cudaGetSymbolAddress((void**)&gi_ctx,  g_gi_ctx);
    cudaGetSymbolAddress((void**)&seq_ctx, g_seq_ctx);
    cudaGetSymbolAddress((void**)&h_ctx,   g_h_ctx);
    cudaGetSymbolAddress((void**)&mem,     g_mem);
    cudaGetSymbolAddress((void**)&xr,      g_xr);
    cudaGetSymbolAddress((void**)&xw,      g_xw);
    cudaGetSymbolAddress((void**)&gates,   g_gates);
    cudaGetSymbolAddress((void**)&query,   g_query);
    cudaGetSymbolAddress((void**)&h_att,   g_h_att);

    float* hU0 = h_utt;  float* hU1 = h_utt + 2 * NB * HDIM;
    float* hC0 = h_ctx;  float* hC1 = h_ctx + 2 * NQ * HDIM;
    float* hA0 = h_att;  float* hA1 = h_att + 2 * NQ * HDIM;

    const int GRU_SMEM = (18000 + 4800 * 4) * 4;   // 148800 B
    const int ATT_SMEM = (12000 + 4800 * 4) * 4;   // 124800 B
    cudaFuncSetAttribute(gru_step3<0>, cudaFuncAttributeMaxDynamicSharedMemorySize, GRU_SMEM);
    cudaFuncSetAttribute(gru_step3<1>, cudaFuncAttributeMaxDynamicSharedMemorySize, GRU_SMEM);
    cudaFuncSetAttribute(att_step3,    cudaFuncAttributeMaxDynamicSharedMemorySize, ATT_SMEM);

    cudaStream_t s = 0;

    // ---- utterance GRU input projection (gathered emb) ----
    {
        dim3 g((1800 + GTN - 1) / GTN, (LSEQ * NB + GTM - 1) / GTM);
        gemm3<1><<<g, 256, 0, s>>>(nullptr, 0, utt_Wih, utt_bih,
                                   gi_utt, 1800, LSEQ * NB, 1800, EDIM, emb, ids);
    }
    // ---- utterance GRU scan (64 per-step launches; t==0 path needs no init) ----
    {
        dim3 g(30, 2, 2);
        int cur = 0;
        for (int t = 0; t < LSEQ; t++) {
            gru_step3<0><<<g, 320, GRU_SMEM, s>>>(cur ? hU1 : hU0, cur ? hU0 : hU1,
                                                  gi_utt, utt_Whh, utt_bhh, seq_lens,
                                                  maxpool, nullptr, t, NB, LSEQ);
            cur ^= 1;
        }
    }
    // ---- u = tanh(maxpool @ lin_w^T + lin_b) ----
    lin_kernel<<<NB, 256, 0, s>>>(maxpool, lin_w, lin_b, u);

    // ---- context windows + ctx GRU ----
    build_inp0<<<(KF * NQ * HDIM + 255) / 256, 256, 0, s>>>(u, inp0);
    {
        dim3 g((1800 + GTN - 1) / GTN, (KF * NQ + GTM - 1) / GTM);
        gemm3<0><<<g, 256, 0, s>>>(inp0, HDIM, ctx_Wih, ctx_bih,
                                   gi_ctx, 1800, KF * NQ, 1800, HDIM, nullptr, nullptr);
    }
    {
        dim3 g(30, 2, 2);
        int cur = 0;
        for (int t = 0; t < KF; t++) {
            gru_step3<1><<<g, 320, GRU_SMEM, s>>>(cur ? hC1 : hC0, cur ? hC0 : hC1,
                                                  gi_ctx, ctx_Whh, ctx_bhh, nullptr,
                                                  nullptr, seq_ctx, t, NQ, KF);
            cur ^= 1;
        }
    }
    membank_kernel<<<(KF * NQ * HDIM + 255) / 256, 256, 0, s>>>(inp0, seq_ctx, mem);

    // ---- attention x-projections (hop-invariant; one GEMM each) ----
    {
        dim3 g((1800 + GTN - 1) / GTN, (KF * NQ + GTM - 1) / GTM);
        gemm3<0><<<g, 256, 0, s>>>(mem, HDIM, aWr_w, aWr_b,
                                   xr, 1800, KF * NQ, 1800, HDIM, nullptr, nullptr);
        gemm3<0><<<g, 256, 0, s>>>(mem, HDIM, aW_w, aW_b,
                                   xw, 1800, KF * NQ, 1800, HDIM, nullptr, nullptr);
    }

    // ---- query init + hops ----
    cudaMemcpyAsync(query, u + HDIM, NQ * HDIM * sizeof(float),
                    cudaMemcpyDeviceToDevice, s);
    dim3 ga(30, 2, 2);
    for (int hop = 0; hop < NHOPS; hop++) {
        score_kernel<<<NQ, 128, 0, s>>>(query, mem, gates);
        int cur = 0;
        for (int t = 0; t < KF; t++) {
            att_step3<<<ga, 320, ATT_SMEM, s>>>(cur ? hA1 : hA0, cur ? hA0 : hA1,
                                                xr, xw, aUr_w, aU_w, aUr_b, aU_b,
                                                gates, t, hop);
            cur ^= 1;
        }
        // KF=40 even: final state in hA0
        add2_kernel<<<(NQ * HDIM + 255) / 256, 256, 0, s>>>(
            query, hA0, hA0 + NQ * HDIM, NQ * HDIM);
    }

    // ---- classifier ----
    cls_kernel<<<NB, 192, 0, s>>>(u, query, cls_w, cls_b, out);
}

// round 11
// speedup vs baseline: 2.4126x; 1.1574x over previous
#include <cuda_runtime.h>
#include <math.h>

#define NB   128   // N dialogues
#define LSEQ 64    // L
#define EDIM 300
#define HDIM 300
#define KF   40    // KEFF
#define NQ   127   // N-1
#define NHOPS 3
#define NCLS 6

typedef unsigned long long u64;

// ---------------- scratch (device globals; no allocation) ----------------
__device__ float g_gi_utt[(size_t)LSEQ * NB * 1800];     // [t*128+b, 1800]
__device__ float g_h_utt[2][2 * NB * HDIM];
__device__ float g_maxpool[NB * 2 * HDIM];
__device__ float g_u[NB * HDIM];
__device__ float g_inp0[KF * NQ * HDIM];                 // ctx_t time-major
__device__ float g_gi_ctx[(size_t)KF * NQ * 1800];
__device__ float g_seq_ctx[2 * KF * NQ * HDIM];          // [dir, t, i, j]
__device__ float g_h_ctx[2][2 * NQ * HDIM];
__device__ float g_mem[KF * NQ * HDIM];                  // time-major [k,i,j]
__device__ float g_xr[(size_t)KF * NQ * 1800];
__device__ float g_xw[(size_t)KF * NQ * 1800];
__device__ float g_gates[KF * NQ];
__device__ float g_query[NQ * HDIM];
__device__ float g_h_att[2][2 * NQ * HDIM];

__device__ __forceinline__ float sigf(float x) { return 1.f / (1.f + expf(-x)); }

// ---------------- packed f32x2 helpers ----------------
__device__ __forceinline__ u64 pk2(float x, float y) {
    u64 r; asm("mov.b64 %0, {%1, %2};" : "=l"(r) : "f"(x), "f"(y)); return r;
}
__device__ __forceinline__ float2 unpk(u64 v) {
    float2 f; asm("mov.b64 {%0, %1}, %2;" : "=f"(f.x), "=f"(f.y) : "l"(v)); return f;
}
__device__ __forceinline__ u64 f2fma(u64 a, u64 b, u64 c) {
    u64 d; asm("fma.rn.f32x2 %0, %1, %2, %3;" : "=l"(d) : "l"(a), "l"(b), "l"(c));
    return d;
}
__device__ __forceinline__ u64 f2add(u64 a, u64 b) {
    u64 d; asm("add.rn.f32x2 %0, %1, %2;" : "=l"(d) : "l"(a), "l"(b));
    return d;
}
__device__ __forceinline__ float hsum2(u64 v) {
    float2 f = unpk(v); return f.x + f.y;
}

// ---------------- GEMM (f32x2): C = A(MxK) @ W(NxK)^T + bias ----------------
#define GTM 64
#define GTN 64
#define GTK 16

template<int GATHER>
__global__ __launch_bounds__(256)
void gemm3(const float* __restrict__ A, int lda,
           const float* __restrict__ W,
           const float* __restrict__ bias,
           float* __restrict__ C, int ldc,
           int M, int N, int K,
           const float* __restrict__ emb,
           const int* __restrict__ ids)
{
    __shared__ __align__(16) u64   Ad[GTK][66];   // A dup'd: (a,a) per [kk][mm]
    __shared__ __align__(16) float Bs[GTK][66];
    __shared__ int rowid[GTM];
    const int tid = threadIdx.x;
    const int m0 = blockIdx.y * GTM;
    const int n0 = blockIdx.x * GTN;

    if (GATHER) {
        if (tid < GTM) {
            int m = m0 + tid;
            int t = m >> 7, b = m & 127;          // m = t*128 + b
            rowid[tid] = (m < M) ? ids[b * LSEQ + t] : 0;
        }
        __syncthreads();
    }

    u64 acc[4][2] = {};
    const int mt = tid >> 4;   // 0..15
    const int nt = tid & 15;   // 0..15

    for (int k0 = 0; k0 < K; k0 += GTK) {
#pragma unroll
        for (int i = 0; i < 4; i++) {
            int idx = tid + i * 256;
            int mm = idx >> 4, kk = idx & 15;
            int m = m0 + mm, k = k0 + kk;
            float v = 0.f;
            if (m < M && k < K) {
                if (GATHER) v = emb[(size_t)rowid[mm] * K + k];
                else        v = A[(size_t)m * lda + k];
            }
            Ad[kk][mm] = pk2(v, v);
        }
#pragma unroll
        for (int i = 0; i < 4; i++) {
            int idx = tid + i * 256;
            int nn = idx >> 4, kk = idx & 15;
            int n = n0 + nn, k = k0 + kk;
            Bs[kk][nn] = (n < N && k < K) ? W[(size_t)n * K + k] : 0.f;
        }
        __syncthreads();
#pragma unroll
        for (int kk = 0; kk < GTK; kk++) {
            ulonglong2 a01 = *(const ulonglong2*)&Ad[kk][mt * 4];
            ulonglong2 a23 = *(const ulonglong2*)&Ad[kk][mt * 4 + 2];
            u64 b0 = *(const u64*)&Bs[kk][nt * 4];
            u64 b1 = *(const u64*)&Bs[kk][nt * 4 + 2];
            acc[0][0] = f2fma(a01.x, b0, acc[0][0]);
            acc[0][1] = f2fma(a01.x, b1, acc[0][1]);
            acc[1][0] = f2fma(a01.y, b0, acc[1][0]);
            acc[1][1] = f2fma(a01.y, b1, acc[1][1]);
            acc[2][0] = f2fma(a23.x, b0, acc[2][0]);
            acc[2][1] = f2fma(a23.x, b1, acc[2][1]);
            acc[3][0] = f2fma(a23.y, b0, acc[3][0]);
            acc[3][1] = f2fma(a23.y, b1, acc[3][1]);
        }
        __syncthreads();
    }
#pragma unroll
    for (int i = 0; i < 4; i++) {
        int m = m0 + mt * 4 + i;
        if (m >= M) continue;
#pragma unroll
        for (int p = 0; p < 2; p++) {
            float2 v = unpk(acc[i][p]);
            int n = n0 + nt * 4 + 2 * p;
            if (n < N)     C[(size_t)m * ldc + n]     = v.x + bias[n];
            if (n + 1 < N) C[(size_t)m * ldc + n + 1] = v.y + bias[n + 1];
        }
    }
}

// ---------------- GRU step v4b: k-packed f32x2, 960 threads, k-split 3 ------
// Grid (30 jgrp, 2 bgrp, 2 dir), 960 threads = brow(32) x uu(10) x kthird(3).
// Unit strides below are in ulonglong2 (= 4 floats):
//   gate stride   = 10 rows * 300 floats = 3000 floats = 750 ull2
//   b_hi stride   = 32 rows * 300 floats = 9600 floats = 2400 ull2
// MODE 0: utt (mask + reversed gi + maxpool) | MODE 1: ctx (seqout)
template<int MODE>
__global__ __launch_bounds__(960, 1)
void gru_step4(const float* __restrict__ hp, float* __restrict__ hn,
               const float* __restrict__ gi,      // [T*B, 1800]
               const float* __restrict__ Whh,     // [2,900,300]
               const float* __restrict__ bhh,     // [2,900]
               const int*   __restrict__ seq_lens,
               float* __restrict__ maxpool,       // [B, 600]
               float* __restrict__ seqout,        // [2,T,B,300]
               int t, int B, int T)
{
    extern __shared__ float sm[];
    float* Ws = sm;            // [30][300] natural  (36000 B)
    float* Hs = sm + 9000;     // [64][300] natural  (76800 B)

    const int tid    = threadIdx.x;
    const int brow   = tid & 31;
    const int uu     = (tid >> 5) % 10;
    const int kthird = tid / 320;
    const int jgrp = blockIdx.x, bgrp = blockIdx.y, dir = blockIdx.z;
    const int j = jgrp * 10 + uu;
    const int dirbase = dir * B * HDIM;
    const int b0 = bgrp * 64;
    const int b_lo = b0 + brow, b_hi = b_lo + 32;

    if (t > 0) {
        // stage weights: 30 rows x 75 float4 (natural layout)
        for (int idx = tid; idx < 2250; idx += 960) {
            int row = idx / 75, q = idx % 75;
            int g = row / 10, ju = row % 10;
            ((float4*)Ws)[row * 75 + q] = ((const float4*)(Whh +
                ((size_t)dir * 900 + g * 300 + jgrp * 10 + ju) * 300))[q];
        }
        // stage h: 64 rows x 75 float4 (natural layout)
        for (int idx = tid; idx < 4800; idx += 960) {
            int bl = idx / 75, q = idx % 75;
            int b = b0 + bl;
            float4 v = make_float4(0.f, 0.f, 0.f, 0.f);
            if (b < B) v = ((const float4*)(hp + dirbase + (size_t)b * 300))[q];
            ((float4*)Hs)[idx] = v;
        }
    }

    // epilogue prefetch (kthird==0 threads own the epilogue)
    float grA[3], grB[3], holdA = 0.f, holdB = 0.f, mpA = -1e30f, mpB = -1e30f;
    float bhr = 0.f, bhz = 0.f, bhn = 0.f;
    bool mA = true, mB = true;
    if (kthird == 0) {
        int lenA = T, lenB = T;
        if (b_lo < B) {
            if (MODE == 0) { lenA = seq_lens[b_lo]; mA = (t < lenA); }
            int trow = (MODE == 0) ? ((dir == 0) ? t : max(lenA - 1 - t, 0))
                                   : ((dir == 0) ? t : (T - 1 - t));
            const float* gr = gi + ((size_t)trow * B + b_lo) * 1800 + dir * 900 + j;
            grA[0] = gr[0]; grA[1] = gr[300]; grA[2] = gr[600];
            if (t > 0) holdA = hp[dirbase + (size_t)b_lo * 300 + j];
            if (MODE == 0 && t > 0) mpA = maxpool[b_lo * (2 * HDIM) + dir * HDIM + j];
        }
        if (b_hi < B) {
            if (MODE == 0) { lenB = seq_lens[b_hi]; mB = (t < lenB); }
            int trow = (MODE == 0) ? ((dir == 0) ? t : max(lenB - 1 - t, 0))
                                   : ((dir == 0) ? t : (T - 1 - t));
            const float* gr = gi + ((size_t)trow * B + b_hi) * 1800 + dir * 900 + j;
            grB[0] = gr[0]; grB[1] = gr[300]; grB[2] = gr[600];
            if (t > 0) holdB = hp[dirbase + (size_t)b_hi * 300 + j];
            if (MODE == 0 && t > 0) mpB = maxpool[b_hi * (2 * HDIM) + dir * HDIM + j];
        }
        bhr = bhh[dir * 900 + j];
        bhz = bhh[dir * 900 + 300 + j];
        bhn = bhh[dir * 900 + 600 + j];
    }
    __syncthreads();

    u64 arA = 0ULL, azA = 0ULL, anA = 0ULL;
    u64 arB = 0ULL, azB = 0ULL, anB = 0ULL;
    if (t > 0) {
        const ulonglong2* wr = (const ulonglong2*)(Ws + uu * 300 + kthird * 100);
        const ulonglong2* hA = (const ulonglong2*)(Hs + brow * 300 + kthird * 100);
#pragma unroll 5
        for (int q = 0; q < 25; q++) {
            ulonglong2 w0 = wr[q], w1 = wr[q + 750], w2 = wr[q + 1500];
            ulonglong2 ha = hA[q], hb = hA[q + 2400];
            arA = f2fma(ha.x, w0.x, arA); arA = f2fma(ha.y, w0.y, arA);
            azA = f2fma(ha.x, w1.x, azA); azA = f2fma(ha.y, w1.y, azA);
            anA = f2fma(ha.x, w2.x, anA); anA = f2fma(ha.y, w2.y, anA);
            arB = f2fma(hb.x, w0.x, arB); arB = f2fma(hb.y, w0.y, arB);
            azB = f2fma(hb.x, w1.x, azB); azB = f2fma(hb.y, w1.y, azB);
            anB = f2fma(hb.x, w2.x, anB); anB = f2fma(hb.y, w2.y, anB);
        }
        // reduce kthird partials via smem (overlay Ws region)
        __syncthreads();
        u64* red = (u64*)sm;
        if (kthird > 0) {
            int s6 = ((kthird - 1) * 320 + (tid - 320 * kthird)) * 6;
            red[s6 + 0] = arA; red[s6 + 1] = azA; red[s6 + 2] = anA;
            red[s6 + 3] = arB; red[s6 + 4] = azB; red[s6 + 5] = anB;
        }
        __syncthreads();
        if (kthird == 0) {
#pragma unroll
            for (int kt = 0; kt < 2; kt++) {
                int s6 = (kt * 320 + tid) * 6;
                arA = f2add(arA, red[s6 + 0]);
                azA = f2add(azA, red[s6 + 1]);
                anA = f2add(anA, red[s6 + 2]);
                arB = f2add(arB, red[s6 + 3]);
                azB = f2add(azB, red[s6 + 4]);
                anB = f2add(anB, red[s6 + 5]);
            }
        }
    }

    if (kthird != 0) return;
    if (b_lo < B) {
        float r = sigf(grA[0] + hsum2(arA) + bhr);
        float z = sigf(grA[1] + hsum2(azA) + bhz);
        float n = tanhf(grA[2] + r * (hsum2(anA) + bhn));
        float hnew = (1.f - z) * n + z * holdA;
        if (MODE == 0) {
            hn[dirbase + (size_t)b_lo * 300 + j] = mA ? hnew : holdA;
            maxpool[b_lo * (2 * HDIM) + dir * HDIM + j] = fmaxf(mpA, mA ? hnew : 0.f);
        } else {
            hn[dirbase + (size_t)b_lo * 300 + j] = hnew;
            seqout[(((size_t)dir * T + t) * B + b_lo) * 300 + j] = hnew;
        }
    }
    if (b_hi < B) {
        float r = sigf(grB[0] + hsum2(arB) + bhr);
        float z = sigf(grB[1] + hsum2(azB) + bhz);
        float n = tanhf(grB[2] + r * (hsum2(anB) + bhn));
        float hnew = (1.f - z) * n + z * holdB;
        if (MODE == 0) {
            hn[dirbase + (size_t)b_hi * 300 + j] = mB ? hnew : holdB;
            maxpool[b_hi * (2 * HDIM) + dir * HDIM + j] = fmaxf(mpB, mB ? hnew : 0.f);
        } else {
            hn[dirbase + (size_t)b_hi * 300 + j] = hnew;
            seqout[(((size_t)dir * T + t) * B + b_hi) * 300 + j] = hnew;
        }
    }
}

// ---------------- attention-GRU step v4b ----------------
__global__ __launch_bounds__(960, 1)
void att_step4(const float* __restrict__ hp, float* __restrict__ hn,
               const float* __restrict__ xr,   // [40*127, 1800]
               const float* __restrict__ xw,
               const float* __restrict__ Ur,   // [3,2,300,300]
               const float* __restrict__ Uw,
               const float* __restrict__ bur,  // [3,2,300]
               const float* __restrict__ bu,
               const float* __restrict__ gates, // [40*127]
               int t, int hop)
{
    extern __shared__ float sm[];
    float* Ws = sm;            // [20][300]  (24000 B)
    float* Hs = sm + 6000;     // [64][300]

    const int tid    = threadIdx.x;
    const int brow   = tid & 31;
    const int uu     = (tid >> 5) % 10;
    const int kthird = tid / 320;
    const int jgrp = blockIdx.x, bgrp = blockIdx.y, dir = blockIdx.z;
    const int j = jgrp * 10 + uu;
    const int wd = hop * 2 + dir;
    const int dirbase = dir * NQ * HDIM;
    const int b0 = bgrp * 64;
    const int b_lo = b0 + brow, b_hi = b_lo + 32;

    if (t > 0) {
        for (int idx = tid; idx < 1500; idx += 960) {
            int row = idx / 75, q = idx % 75;
            int g = row / 10, ju = row % 10;
            const float* Wsrc = g ? Uw : Ur;
            ((float4*)Ws)[row * 75 + q] = ((const float4*)(Wsrc +
                ((size_t)wd * 300 + jgrp * 10 + ju) * 300))[q];
        }
        for (int idx = tid; idx < 4800; idx += 960) {
            int bl = idx / 75, q = idx % 75;
            int b = b0 + bl;
            float4 v = make_float4(0.f, 0.f, 0.f, 0.f);
            if (b < NQ) v = ((const float4*)(hp + dirbase + (size_t)b * 300))[q];
            ((float4*)Hs)[idx] = v;
        }
    }

    const int tt = (dir == 0) ? t : (KF - 1 - t);
    float xrA = 0.f, xwA = 0.f, gA = 0.f, holdA = 0.f;
    float xrB = 0.f, xwB = 0.f, gB = 0.f, holdB = 0.f;
    float burv = 0.f, buv = 0.f;
    if (kthird == 0) {
        if (b_lo < NQ) {
            size_t xrow = ((size_t)tt * NQ + b_lo) * 1800 + wd * 300 + j;
            xrA = xr[xrow]; xwA = xw[xrow]; gA = gates[tt * NQ + b_lo];
            if (t > 0) holdA = hp[dirbase + (size_t)b_lo * 300 + j];
        }
        if (b_hi < NQ) {
            size_t xrow = ((size_t)tt * NQ + b_hi) * 1800 + wd * 300 + j;
            xrB = xr[xrow]; xwB = xw[xrow]; gB = gates[tt * NQ + b_hi];
            if (t > 0) holdB = hp[dirbase + (size_t)b_hi * 300 + j];
        }
        burv = bur[wd * 300 + j];
        buv  = bu[wd * 300 + j];
    }
    __syncthreads();

    u64 arA = 0ULL, awA = 0ULL, arB = 0ULL, awB = 0ULL;
    if (t > 0) {
        const ulonglong2* wr = (const ulonglong2*)(Ws + uu * 300 + kthird * 100);
        const ulonglong2* hA = (const ulonglong2*)(Hs + brow * 300 + kthird * 100);
#pragma unroll 5
        for (int q = 0; q < 25; q++) {
            ulonglong2 w0 = wr[q], w1 = wr[q + 750];
            ulonglong2 ha = hA[q], hb = hA[q + 2400];
            arA = f2fma(ha.x, w0.x, arA); arA = f2fma(ha.y, w0.y, arA);
            awA = f2fma(ha.x, w1.x, awA); awA = f2fma(ha.y, w1.y, awA);
            arB = f2fma(hb.x, w0.x, arB); arB = f2fma(hb.y, w0.y, arB);
            awB = f2fma(hb.x, w1.x, awB); awB = f2fma(hb.y, w1.y, awB);
        }
        __syncthreads();
        u64* red = (u64*)sm;
        if (kthird > 0) {
            int s4 = ((kthird - 1) * 320 + (tid - 320 * kthird)) * 4;
            red[s4 + 0] = arA; red[s4 + 1] = awA;
            red[s4 + 2] = arB; red[s4 + 3] = awB;
        }
        __syncthreads();
        if (kthird == 0) {
#pragma unroll
            for (int kt = 0; kt < 2; kt++) {
                int s4 = (kt * 320 + tid) * 4;
                arA = f2add(arA, red[s4 + 0]);
                awA = f2add(awA, red[s4 + 1]);
                arB = f2add(arB, red[s4 + 2]);
                awB = f2add(awB, red[s4 + 3]);
            }
        }
    }

    if (kthird != 0) return;
    if (b_lo < NQ) {
        float r  = sigf(xrA + hsum2(arA) + burv);
        float ht = tanhf(xwA + r * (hsum2(awA) + buv));
        hn[dirbase + (size_t)b_lo * 300 + j] = gA * ht + (1.f - gA) * holdA;
    }
    if (b_hi < NQ) {
        float r  = sigf(xrB + hsum2(arB) + burv);
        float ht = tanhf(xwB + r * (hsum2(awB) + buv));
        hn[dirbase + (size_t)b_hi * 300 + j] = gB * ht + (1.f - gB) * holdB;
    }
}

// ---------------- small kernels ----------------
__global__ __launch_bounds__(256)
void lin_kernel(const float* __restrict__ mp, const float* __restrict__ w,
                const float* __restrict__ bsc, float* __restrict__ u) {
    int b = blockIdx.x;
    __shared__ float m[600];
    for (int i = threadIdx.x; i < 600; i += 256) m[i] = mp[b * 600 + i];
    __syncthreads();
    int wid = threadIdx.x >> 5, lane = threadIdx.x & 31;
    for (int j = wid; j < HDIM; j += 8) {
        float acc = 0.f;
        const float* wr = w + (size_t)j * 600;
        for (int k = lane; k < 600; k += 32) acc += m[k] * wr[k];
        for (int o = 16; o > 0; o >>= 1) acc += __shfl_xor_sync(0xffffffffu, acc, o);
        if (lane == 0) u[b * HDIM + j] = tanhf(acc + bsc[j]);
    }
}

__global__ void build_inp0(const float* __restrict__ u, float* __restrict__ inp0) {
    int idx = blockIdx.x * blockDim.x + threadIdx.x;
    if (idx >= KF * NQ * HDIM) return;
    int j = idx % HDIM;
    int r = idx / HDIM;
    int i = r % NQ;
    int k = r / NQ;
    int src = (i + 1) - KF + k;
    inp0[idx] = (src >= 0) ? u[src * HDIM + j] : 0.f;
}

__global__ void membank_kernel(const float* __restrict__ inp0,
                               const float* __restrict__ seq,
                               float* __restrict__ mem) {
    int idx = blockIdx.x * blockDim.x + threadIdx.x;
    if (idx >= KF * NQ * HDIM) return;
    int j = idx % HDIM;
    int r = idx / HDIM;
    int i = r % NQ;
    int k = r / NQ;
    float f = seq[((size_t)k) * NQ * HDIM + i * HDIM + j];
    float b = seq[((size_t)KF + (KF - 1 - k)) * NQ * HDIM + i * HDIM + j];
    mem[idx] = inp0[idx] + f + b;
}

__global__ void score_kernel(const float* __restrict__ query,
                             const float* __restrict__ mem,
                             float* __restrict__ gates) {
    int b = blockIdx.x;                 // 0..126
    int tid = threadIdx.x;              // 128
    int lane = tid & 31, w = tid >> 5;
    __shared__ float q[HDIM];
    __shared__ float logit[KF];
    for (int i = tid; i < HDIM; i += 128) q[i] = query[b * HDIM + i];
    __syncthreads();
    for (int k = w; k < KF; k += 4) {
        const float* mrow = mem + ((size_t)k * NQ + b) * HDIM;
        float s = 0.f;
        for (int i = lane; i < HDIM; i += 32) s += q[i] * mrow[i];
        for (int o = 16; o > 0; o >>= 1) s += __shfl_xor_sync(0xffffffffu, s, o);
        if (lane == 0) logit[k] = (k >= KF - 1 - b) ? s : -1e10f;
    }
    __syncthreads();
    if (w == 0) {
        float m = -INFINITY;
        for (int k = lane; k < KF; k += 32) m = fmaxf(m, logit[k]);
        for (int o = 16; o > 0; o >>= 1) m = fmaxf(m, __shfl_xor_sync(0xffffffffu, m, o));
        float ssum = 0.f;
        for (int k = lane; k < KF; k += 32) { float e = expf(logit[k] - m); logit[k] = e; ssum += e; }
        for (int o = 16; o > 0; o >>= 1) ssum += __shfl_xor_sync(0xffffffffu, ssum, o);
        for (int k = lane; k < KF; k += 32) gates[k * NQ + b] = logit[k] / ssum;
    }
}

__global__ void add2_kernel(float* __restrict__ q,
                            const float* __restrict__ hf,
                            const float* __restrict__ hb, int n) {
    int i = blockIdx.x * blockDim.x + threadIdx.x;
    if (i < n) q[i] += hf[i] + hb[i];
}

__global__ void cls_kernel(const float* __restrict__ u,
                           const float* __restrict__ query,
                           const float* __restrict__ cls_w,
                           const float* __restrict__ cls_b,
                           float* __restrict__ out) {
    int row = blockIdx.x;               // 0..127
    int w = threadIdx.x >> 5, lane = threadIdx.x & 31;   // 192 threads = 6 warps
    const float* s = (row == 0) ? u : (query + (row - 1) * HDIM);
    float acc = 0.f;
    for (int i = lane; i < HDIM; i += 32) acc += s[i] * cls_w[w * HDIM + i];
    for (int o = 16; o > 0; o >>= 1) acc += __shfl_xor_sync(0xffffffffu, acc, o);
    if (lane == 0) out[row * NCLS + w] = acc + cls_b[w];
}

// ---------------- host orchestration ----------------
extern "C" void kernel_launch(void* const* d_in, const int* in_sizes, int n_in,
                              void* d_out, int out_size) {
    const int*   ids      = (const int*)d_in[0];
    const int*   seq_lens = (const int*)d_in[1];
    const float* emb      = (const float*)d_in[2];
    const float* utt_Wih  = (const float*)d_in[3];
    const float* utt_Whh  = (const float*)d_in[4];
    const float* utt_bih  = (const float*)d_in[5];
    const float* utt_bhh  = (const float*)d_in[6];
    const float* lin_w    = (const float*)d_in[7];
    const float* lin_b    = (const float*)d_in[8];
    const float* ctx_Wih  = (const float*)d_in[9];
    const float* ctx_Whh  = (const float*)d_in[10];
    const float* ctx_bih  = (const float*)d_in[11];
    const float* ctx_bhh  = (const float*)d_in[12];
    const float* aWr_w    = (const float*)d_in[13];
    const float* aWr_b    = (const float*)d_in[14];
    const float* aUr_w    = (const float*)d_in[15];
    const float* aUr_b    = (const float*)d_in[16];
    const float* aW_w     = (const float*)d_in[17];
    const float* aW_b     = (const float*)d_in[18];
    const float* aU_w     = (const float*)d_in[19];
    const float* aU_b     = (const float*)d_in[20];
    const float* cls_w    = (const float*)d_in[21];
    const float* cls_b    = (const float*)d_in[22];
    float* out = (float*)d_out;

    float *gi_utt, *h_utt, *maxpool, *u, *inp0, *gi_ctx, *seq_ctx, *h_ctx;
    float *mem, *xr, *xw, *gates, *query, *h_att;
    cudaGetSymbolAddress((void**)&gi_utt,  g_gi_utt);
    cudaGetSymbolAddress((void**)&h_utt,   g_h_utt);
    cudaGetSymbolAddress((void**)&maxpool, g_maxpool);
    cudaGetSymbolAddress((void**)&u,       g_u);
    cudaGetSymbolAddress((void**)&inp0,    g_inp0);
    cudaGetSymbolAddress((void**)&gi_ctx,  g_gi_ctx);
    cudaGetSymbolAddress((void**)&seq_ctx, g_seq_ctx);
    cudaGetSymbolAddress((void**)&h_ctx,   g_h_ctx);
    cudaGetSymbolAddress((void**)&mem,     g_mem);
    cudaGetSymbolAddress((void**)&xr,      g_xr);
    cudaGetSymbolAddress((void**)&xw,      g_xw);
    cudaGetSymbolAddress((void**)&gates,   g_gates);
    cudaGetSymbolAddress((void**)&query,   g_query);
    cudaGetSymbolAddress((void**)&h_att,   g_h_att);

    float* hU0 = h_utt;  float* hU1 = h_utt + 2 * NB * HDIM;
    float* hC0 = h_ctx;  float* hC1 = h_ctx + 2 * NQ * HDIM;
    float* hA0 = h_att;  float* hA1 = h_att + 2 * NQ * HDIM;

    const int GRU_SMEM = (9000 + 64 * 300) * 4;   // 112800 B
    const int ATT_SMEM = (6000 + 64 * 300) * 4;   // 100800 B
    cudaFuncSetAttribute(gru_step4<0>, cudaFuncAttributeMaxDynamicSharedMemorySize, GRU_SMEM);
    cudaFuncSetAttribute(gru_step4<1>, cudaFuncAttributeMaxDynamicSharedMemorySize, GRU_SMEM);
    cudaFuncSetAttribute(att_step4,    cudaFuncAttributeMaxDynamicSharedMemorySize, ATT_SMEM);

    cudaStream_t s = 0;

    // ---- utterance GRU input projection (gathered emb) ----
    {
        dim3 g((1800 + GTN - 1) / GTN, (LSEQ * NB + GTM - 1) / GTM);
        gemm3<1><<<g, 256, 0, s>>>(nullptr, 0, utt_Wih, utt_bih,
                                   gi_utt, 1800, LSEQ * NB, 1800, EDIM, emb, ids);
    }
    // ---- utterance GRU scan ----
    {
        dim3 g(30, 2, 2);
        int cur = 0;
        for (int t = 0; t < LSEQ; t++) {
            gru_step4<0><<<g, 960, GRU_SMEM, s>>>(cur ? hU1 : hU0, cur ? hU0 : hU1,
                                                  gi_utt, utt_Whh, utt_bhh, seq_lens,
                                                  maxpool, nullptr, t, NB, LSEQ);
            cur ^= 1;
        }
    }
    // ---- u = tanh(maxpool @ lin_w^T + lin_b) ----
    lin_kernel<<<NB, 256, 0, s>>>(maxpool, lin_w, lin_b, u);

    // ---- context windows + ctx GRU ----
    build_inp0<<<(KF * NQ * HDIM + 255) / 256, 256, 0, s>>>(u, inp0);
    {
        dim3 g((1800 + GTN - 1) / GTN, (KF * NQ + GTM - 1) / GTM);
        gemm3<0><<<g, 256, 0, s>>>(inp0, HDIM, ctx_Wih, ctx_bih,
                                   gi_ctx, 1800, KF * NQ, 1800, HDIM, nullptr, nullptr);
    }
    {
        dim3 g(30, 2, 2);
        int cur = 0;
        for (int t = 0; t < KF; t++) {
            gru_step4<1><<<g, 960, GRU_SMEM, s>>>(cur ? hC1 : hC0, cur ? hC0 : hC1,
                                                  gi_ctx, ctx_Whh, ctx_bhh, nullptr,
                                                  nullptr, seq_ctx, t, NQ, KF);
            cur ^= 1;
        }
    }
    membank_kernel<<<(KF * NQ * HDIM + 255) / 256, 256, 0, s>>>(inp0, seq_ctx, mem);

    // ---- attention x-projections (hop-invariant; one GEMM each) ----
    {
        dim3 g((1800 + GTN - 1) / GTN, (KF * NQ + GTM - 1) / GTM);
        gemm3<0><<<g, 256, 0, s>>>(mem, HDIM, aWr_w, aWr_b,
                                   xr, 1800, KF * NQ, 1800, HDIM, nullptr, nullptr);
        gemm3<0><<<g, 256, 0, s>>>(mem, HDIM, aW_w, aW_b,
                                   xw, 1800, KF * NQ, 1800, HDIM, nullptr, nullptr);
    }

    // ---- query init + hops ----
    cudaMemcpyAsync(query, u + HDIM, NQ * HDIM * sizeof(float),
                    cudaMemcpyDeviceToDevice, s);
    dim3 ga(30, 2, 2);
    for (int hop = 0; hop < NHOPS; hop++) {
        score_kernel<<<NQ, 128, 0, s>>>(query, mem, gates);
        int cur = 0;
        for (int t = 0; t < KF; t++) {
            att_step4<<<ga, 960, ATT_SMEM, s>>>(cur ? hA1 : hA0, cur ? hA0 : hA1,
                                                xr, xw, aUr_w, aU_w, aUr_b, aU_b,
                                                gates, t, hop);
            cur ^= 1;
        }
        // KF=40 even: final state in hA0
        add2_kernel<<<(NQ * HDIM + 255) / 256, 256, 0, s>>>(
            query, hA0, hA0 + NQ * HDIM, NQ * HDIM);
    }

    // ---- classifier ----
    cls_kernel<<<NB, 192, 0, s>>>(u, query, cls_w, cls_b, out);
}